// round 1
// baseline (speedup 1.0000x reference)
#include <cuda_runtime.h>
#include <cuda_bf16.h>
#include <cstdint>

#define B_  2
#define T_  4096
#define D_  1024
#define H_  16
#define DH_ 64
#define KP_ 4
#define TP_ 1024   // pooled sequence length T/KP

// ---------------- scratch (device globals; no allocations allowed) ----------
__device__ float g_pooled[B_ * TP_ * D_];          // [B, TP, D]
__device__ float g_Q[(size_t)B_ * H_ * T_ * DH_];  // [B, H, T, DH]
__device__ float g_K[(size_t)B_ * H_ * TP_ * DH_]; // [B, H, TP, DH] (compacted rows)
__device__ float g_V[(size_t)B_ * H_ * TP_ * DH_];
__device__ int   g_act[B_ * TP_];                  // compacted active bucket indices
__device__ int   g_cnt[B_];

// ---------------- 1) average pool over KP=4 ---------------------------------
__global__ void pool_kernel(const float* __restrict__ hs) {
    int p = blockIdx.x * blockDim.x + threadIdx.x;   // float4 index, 524288 total
    int d4  = p & 255;          // D/4 = 256
    int row = p >> 8;           // [0, B*TP)
    int b = row >> 10, tt = row & 1023;
    const float4* src = (const float4*)hs;
    size_t base = ((size_t)(b * T_ + tt * KP_)) * 256 + d4;
    float4 s0 = src[base];
    float4 s1 = src[base + 256];
    float4 s2 = src[base + 512];
    float4 s3 = src[base + 768];
    float4 r;
    r.x = (s0.x + s1.x + s2.x + s3.x) * 0.25f;
    r.y = (s0.y + s1.y + s2.y + s3.y) * 0.25f;
    r.z = (s0.z + s1.z + s2.z + s3.z) * 0.25f;
    r.w = (s0.w + s1.w + s2.w + s3.w) * 0.25f;
    ((float4*)g_pooled)[p] = r;
}

// ---------------- 2) mask -> compacted active-key list ----------------------
__global__ void mask_kernel(const int* __restrict__ am) {
    __shared__ int sc[TP_];
    int b = blockIdx.x, tt = threadIdx.x;
    const int* m = am + b * T_ + tt * KP_;
    int s = m[0] + m[1] + m[2] + m[3];
    int act = (s == 0) ? 1 : 0;   // bucket active iff pooled mask mean == 0
    sc[tt] = act;
    __syncthreads();
    // Hillis-Steele inclusive scan over 1024
    for (int off = 1; off < TP_; off <<= 1) {
        int v = 0;
        if (tt >= off) v = sc[tt - off];
        __syncthreads();
        sc[tt] += v;
        __syncthreads();
    }
    int total = sc[TP_ - 1];
    if (total == 0) {
        // all masked: softmax is shift-invariant -> identical to all-active
        g_act[b * TP_ + tt] = tt;
        if (tt == 0) g_cnt[b] = TP_;
    } else {
        if (act) g_act[b * TP_ + sc[tt] - 1] = tt;
        if (tt >= total) g_act[b * TP_ + tt] = 0;  // safe dummy (disjoint region)
        if (tt == 0) g_cnt[b] = total;
    }
}

// ---------------- 3) projection GEMM, C = A @ W^T + b, head-major output ----
// MODE 0: Q  (A = hidden_states, M = 8192, out = g_Q  [B,H,T,DH])
// MODE 1: KV (A = pooled gathered by g_act, out = g_K/g_V compacted [B,H,i,DH])
template<int MODE>
__global__ void __launch_bounds__(256)
gemm_kernel(const float* __restrict__ A,
            const float* __restrict__ Wk_, const float* __restrict__ bk_,
            const float* __restrict__ Wv_, const float* __restrict__ bv_)
{
    __shared__ float As[2][8][128];
    __shared__ float Bs[2][8][128];
    const int tid = threadIdx.x;
    const int bn = blockIdx.x * 128;
    const int bm = blockIdx.y * 128;

    const float* W; const float* bias; float* outp;
    int batch = 0;
    if (MODE == 0) {
        W = Wk_; bias = bk_; outp = g_Q;
    } else {
        batch = blockIdx.z & 1;
        int sel = blockIdx.z >> 1;
        if (bm >= g_cnt[batch]) return;
        W    = sel ? Wv_ : Wk_;
        bias = sel ? bv_ : bk_;
        outp = sel ? g_V : g_K;
    }

    const int aRow = tid >> 1;
    const int aCol = (tid & 1) * 4;

    const float* aPtr;
    if (MODE == 0) {
        aPtr = A + (size_t)(bm + aRow) * D_ + aCol;
    } else {
        int srow = g_act[batch * TP_ + bm + aRow];
        aPtr = g_pooled + ((size_t)batch * TP_ + srow) * D_ + aCol;
    }
    const float* wPtr = W + (size_t)(bn + aRow) * D_ + aCol;

    float acc[8][8];
    #pragma unroll
    for (int i = 0; i < 8; i++)
        #pragma unroll
        for (int j = 0; j < 8; j++) acc[i][j] = 0.0f;

    // preload tile 0
    float4 av = *(const float4*)aPtr;
    float4 wv = *(const float4*)wPtr;
    As[0][aCol + 0][aRow] = av.x; As[0][aCol + 1][aRow] = av.y;
    As[0][aCol + 2][aRow] = av.z; As[0][aCol + 3][aRow] = av.w;
    Bs[0][aCol + 0][aRow] = wv.x; Bs[0][aCol + 1][aRow] = wv.y;
    Bs[0][aCol + 2][aRow] = wv.z; Bs[0][aCol + 3][aRow] = wv.w;
    __syncthreads();

    const int tr = (tid >> 4) * 8;
    const int tc = (tid & 15) * 8;
    int buf = 0;

    for (int kt = 0; kt < D_ / 8; kt++) {
        if (kt < D_ / 8 - 1) {
            av = *(const float4*)(aPtr + (kt + 1) * 8);
            wv = *(const float4*)(wPtr + (kt + 1) * 8);
        }
        #pragma unroll
        for (int k = 0; k < 8; k++) {
            float a[8], bb[8];
            *(float4*)(a)      = *(const float4*)&As[buf][k][tr];
            *(float4*)(a + 4)  = *(const float4*)&As[buf][k][tr + 4];
            *(float4*)(bb)     = *(const float4*)&Bs[buf][k][tc];
            *(float4*)(bb + 4) = *(const float4*)&Bs[buf][k][tc + 4];
            #pragma unroll
            for (int i = 0; i < 8; i++)
                #pragma unroll
                for (int j = 0; j < 8; j++)
                    acc[i][j] = fmaf(a[i], bb[j], acc[i][j]);
        }
        if (kt < D_ / 8 - 1) {
            int nb = buf ^ 1;
            As[nb][aCol + 0][aRow] = av.x; As[nb][aCol + 1][aRow] = av.y;
            As[nb][aCol + 2][aRow] = av.z; As[nb][aCol + 3][aRow] = av.w;
            Bs[nb][aCol + 0][aRow] = wv.x; Bs[nb][aCol + 1][aRow] = wv.y;
            Bs[nb][aCol + 2][aRow] = wv.z; Bs[nb][aCol + 3][aRow] = wv.w;
            __syncthreads();
            buf = nb;
        }
    }

    // epilogue: + bias, scatter to [*, H, L, DH] layout (tc-block never crosses a head)
    const int n0 = bn + tc;
    const int h  = n0 >> 6;
    const int d0 = n0 & 63;
    float bva[4], bvb[4];
    *(float4*)bva = *(const float4*)(bias + n0);
    *(float4*)bvb = *(const float4*)(bias + n0 + 4);
    #pragma unroll
    for (int i = 0; i < 8; i++) {
        int m = bm + tr + i;
        size_t dst;
        if (MODE == 0) {
            int b = m >> 12, l = m & (T_ - 1);
            dst = ((size_t)(b * H_ + h) * T_ + l) * DH_ + d0;
        } else {
            dst = ((size_t)(batch * H_ + h) * TP_ + m) * DH_ + d0;
        }
        float4 r0, r1;
        r0.x = acc[i][0] + bva[0]; r0.y = acc[i][1] + bva[1];
        r0.z = acc[i][2] + bva[2]; r0.w = acc[i][3] + bva[3];
        r1.x = acc[i][4] + bvb[0]; r1.y = acc[i][5] + bvb[1];
        r1.z = acc[i][6] + bvb[2]; r1.w = acc[i][7] + bvb[3];
        *(float4*)(outp + dst)     = r0;
        *(float4*)(outp + dst + 4) = r1;
    }
}

// ---------------- 4) attention over compacted keys, online softmax ----------
// grid: (T/64, H, B), 256 threads. 64 queries/block, key tiles of 32.
__global__ void __launch_bounds__(256)
attn_kernel(float* __restrict__ out)
{
    __shared__ float Qs[64][68];    // [q][d], pre-scaled by 1/sqrt(DH)
    __shared__ float Kst[64][34];   // [d][key] transposed
    __shared__ float Vs[32][68];    // [key][d]
    __shared__ float Ps[64][33];    // [q][key]

    const int b = blockIdx.z, h = blockIdx.y, q0 = blockIdx.x * 64;
    const int tid = threadIdx.x;
    const int tx = tid & 15, ty = tid >> 4;
    const int cnt = g_cnt[b];
    const int ntiles = (cnt + 31) >> 5;

    const float* Qg = g_Q + ((size_t)(b * H_ + h) * T_ + q0) * DH_;
    const float* Kg = g_K + ((size_t)(b * H_ + h) * TP_) * DH_;
    const float* Vg = g_V + ((size_t)(b * H_ + h) * TP_) * DH_;

    for (int idx = tid; idx < 64 * 16; idx += 256) {
        int r = idx >> 4, c4 = (idx & 15) * 4;
        float4 v = *(const float4*)(Qg + (size_t)r * DH_ + c4);
        v.x *= 0.125f; v.y *= 0.125f; v.z *= 0.125f; v.w *= 0.125f;
        *(float4*)&Qs[r][c4] = v;
    }

    float acc[4][4];
    #pragma unroll
    for (int i = 0; i < 4; i++)
        #pragma unroll
        for (int j = 0; j < 4; j++) acc[i][j] = 0.0f;
    float mrow[4], lrow[4];
    #pragma unroll
    for (int i = 0; i < 4; i++) { mrow[i] = -1e30f; lrow[i] = 0.0f; }

    for (int t = 0; t < ntiles; t++) {
        const int kb = t * 32;
        __syncthreads();  // previous tile fully consumed (also covers Qs stores)
        // K tile transposed: conflict-free stores (lanes stride along key)
        for (int idx = tid; idx < 512; idx += 256) {
            int c4 = idx >> 5, key = idx & 31;
            float4 v = *(const float4*)(Kg + (size_t)(kb + key) * DH_ + c4 * 4);
            Kst[c4 * 4 + 0][key] = v.x;
            Kst[c4 * 4 + 1][key] = v.y;
            Kst[c4 * 4 + 2][key] = v.z;
            Kst[c4 * 4 + 3][key] = v.w;
        }
        // V tile natural
        for (int idx = tid; idx < 512; idx += 256) {
            int r = idx >> 4, c4 = (idx & 15) * 4;
            *(float4*)&Vs[r][c4] = *(const float4*)(Vg + (size_t)(kb + r) * DH_ + c4);
        }
        __syncthreads();

        // scores: rows 4*ty.., cols 2*tx..  (Q pre-scaled)
        float s[4][2];
        #pragma unroll
        for (int i = 0; i < 4; i++) { s[i][0] = 0.0f; s[i][1] = 0.0f; }
        #pragma unroll
        for (int d = 0; d < 64; d++) {
            float2 bk2 = *(const float2*)&Kst[d][2 * tx];
            #pragma unroll
            for (int i = 0; i < 4; i++) {
                float a = Qs[4 * ty + i][d];
                s[i][0] = fmaf(a, bk2.x, s[i][0]);
                s[i][1] = fmaf(a, bk2.y, s[i][1]);
            }
        }
        // mask tail keys beyond cnt
        #pragma unroll
        for (int j = 0; j < 2; j++)
            if (kb + 2 * tx + j >= cnt) {
                #pragma unroll
                for (int i = 0; i < 4; i++) s[i][j] = -1e30f;
            }

        // online softmax per row; (m,l) kept redundantly in all 16 lanes
        #pragma unroll
        for (int i = 0; i < 4; i++) {
            float tm = fmaxf(s[i][0], s[i][1]);
            #pragma unroll
            for (int off = 8; off >= 1; off >>= 1)
                tm = fmaxf(tm, __shfl_xor_sync(0xffffffffu, tm, off));
            float mn = fmaxf(mrow[i], tm);
            float p0 = __expf(s[i][0] - mn);
            float p1 = __expf(s[i][1] - mn);
            Ps[4 * ty + i][2 * tx]     = p0;
            Ps[4 * ty + i][2 * tx + 1] = p1;
            float ts = p0 + p1;
            #pragma unroll
            for (int off = 8; off >= 1; off >>= 1)
                ts += __shfl_xor_sync(0xffffffffu, ts, off);
            float alpha = __expf(mrow[i] - mn);
            lrow[i] = lrow[i] * alpha + ts;
            mrow[i] = mn;
            #pragma unroll
            for (int j = 0; j < 4; j++) acc[i][j] *= alpha;
        }
        __syncwarp();   // Ps rows are produced & consumed within the same half-warp

        // ctx += P @ V : rows 4*ty.., dh cols 4*tx..
        #pragma unroll
        for (int kk = 0; kk < 32; kk++) {
            float v4[4];
            *(float4*)v4 = *(const float4*)&Vs[kk][4 * tx];
            #pragma unroll
            for (int i = 0; i < 4; i++) {
                float p = Ps[4 * ty + i][kk];
                #pragma unroll
                for (int j = 0; j < 4; j++)
                    acc[i][j] = fmaf(p, v4[j], acc[i][j]);
            }
        }
    }

    // epilogue: divide by l, write [B, T, H*DH]
    #pragma unroll
    for (int i = 0; i < 4; i++) {
        int row = 4 * ty + i;
        float inv = 1.0f / lrow[i];
        float4 r;
        r.x = acc[i][0] * inv; r.y = acc[i][1] * inv;
        r.z = acc[i][2] * inv; r.w = acc[i][3] * inv;
        *(float4*)(out + ((size_t)(b * T_ + q0 + row)) * D_ + h * DH_ + 4 * tx) = r;
    }
}

// ---------------- launch -----------------------------------------------------
extern "C" void kernel_launch(void* const* d_in, const int* in_sizes, int n_in,
                              void* d_out, int out_size) {
    const float* hs = (const float*)d_in[0];
    const int*   am = (const int*)d_in[1];
    const float* Wq = (const float*)d_in[2];
    const float* bq = (const float*)d_in[3];
    const float* Wk = (const float*)d_in[4];
    const float* bk = (const float*)d_in[5];
    const float* Wv = (const float*)d_in[6];
    const float* bv = (const float*)d_in[7];
    float* out = (float*)d_out;

    pool_kernel<<<(B_ * TP_ * D_ / 4) / 256, 256>>>(hs);
    mask_kernel<<<B_, TP_>>>(am);
    gemm_kernel<0><<<dim3(D_ / 128, (B_ * T_) / 128, 1), 256>>>(hs, Wq, bq, nullptr, nullptr);
    gemm_kernel<1><<<dim3(D_ / 128, TP_ / 128, 2 * B_), 256>>>(nullptr, Wk, bk, Wv, bv);
    attn_kernel<<<dim3(T_ / 64, H_, B_), 256>>>(out);
}

// round 3
// speedup vs baseline: 1.9435x; 1.9435x over previous
#include <cuda_runtime.h>
#include <cuda_bf16.h>
#include <cstdint>

#define B_  2
#define T_  4096
#define D_  1024
#define H_  16
#define DH_ 64
#define KP_ 4
#define TP_ 1024

// ---------------- scratch (device globals; no allocations allowed) ----------
__device__ __nv_bfloat16 g_hs_hi[(size_t)B_ * T_ * D_];
__device__ __nv_bfloat16 g_hs_lo[(size_t)B_ * T_ * D_];
__device__ __nv_bfloat16 g_phi[B_ * TP_ * D_];
__device__ __nv_bfloat16 g_plo[B_ * TP_ * D_];
__device__ __nv_bfloat16 g_Wq_hi[D_ * D_], g_Wq_lo[D_ * D_];
__device__ __nv_bfloat16 g_Wk_hi[D_ * D_], g_Wk_lo[D_ * D_];
__device__ __nv_bfloat16 g_Wv_hi[D_ * D_], g_Wv_lo[D_ * D_];
__device__ float g_Q[(size_t)B_ * H_ * T_ * DH_];   // [B,H,T,DH]
__device__ float g_K[(size_t)B_ * H_ * TP_ * DH_];  // [B,H,TP,DH] compacted
__device__ float g_V[(size_t)B_ * H_ * TP_ * DH_];
__device__ int   g_act[B_ * TP_];
__device__ int   g_cnt[B_];

// ---------------- helpers ----------------------------------------------------
__device__ __forceinline__ uint32_t smem_u32(const void* p) {
    uint32_t a;
    asm("{ .reg .u64 t; cvta.to.shared.u64 t, %1; cvt.u32.u64 %0, t; }" : "=r"(a) : "l"(p));
    return a;
}
#define CP_ASYNC16(dst, src) \
    asm volatile("cp.async.cg.shared.global [%0], [%1], 16;" :: "r"(dst), "l"(src))
#define CP_COMMIT() asm volatile("cp.async.commit_group;" ::: "memory")

__device__ __forceinline__ void mma_bf16(float* c,
        uint32_t a0, uint32_t a1, uint32_t a2, uint32_t a3,
        uint32_t b0, uint32_t b1) {
    asm volatile("mma.sync.aligned.m16n8k16.row.col.f32.bf16.bf16.f32 "
        "{%0,%1,%2,%3}, {%4,%5,%6,%7}, {%8,%9}, {%0,%1,%2,%3};"
        : "+f"(c[0]), "+f"(c[1]), "+f"(c[2]), "+f"(c[3])
        : "r"(a0), "r"(a1), "r"(a2), "r"(a3), "r"(b0), "r"(b1));
}

// ---------------- 1) fp32 -> bf16 hi/lo split --------------------------------
__global__ void split_kernel(const float* __restrict__ in,
                             __nv_bfloat16* __restrict__ hi,
                             __nv_bfloat16* __restrict__ lo, int n4) {
    int p = blockIdx.x * blockDim.x + threadIdx.x;
    if (p >= n4) return;
    float4 v = ((const float4*)in)[p];
    ushort4 h, l;
    const float* vv = &v.x;
    unsigned short* hp = &h.x; unsigned short* lp = &l.x;
    #pragma unroll
    for (int i = 0; i < 4; i++) {
        __nv_bfloat16 bh = __float2bfloat16(vv[i]);
        float f = vv[i] - __bfloat162float(bh);
        hp[i] = __bfloat16_as_ushort(bh);
        lp[i] = __bfloat16_as_ushort(__float2bfloat16(f));
    }
    ((ushort4*)hi)[p] = h;
    ((ushort4*)lo)[p] = l;
}

// ---------------- 2) avgpool + split ----------------------------------------
__global__ void pool_split_kernel(const float* __restrict__ hs) {
    int p = blockIdx.x * blockDim.x + threadIdx.x;   // float4 index over B*TP*D/4
    int d4  = p & 255;
    int row = p >> 8;
    int b = row >> 10, tt = row & 1023;
    const float4* src = (const float4*)hs;
    size_t base = ((size_t)(b * T_ + tt * KP_)) * 256 + d4;
    float4 s0 = src[base], s1 = src[base + 256], s2 = src[base + 512], s3 = src[base + 768];
    float m[4];
    m[0] = (s0.x + s1.x + s2.x + s3.x) * 0.25f;
    m[1] = (s0.y + s1.y + s2.y + s3.y) * 0.25f;
    m[2] = (s0.z + s1.z + s2.z + s3.z) * 0.25f;
    m[3] = (s0.w + s1.w + s2.w + s3.w) * 0.25f;
    ushort4 h, l;
    unsigned short* hp = &h.x; unsigned short* lp = &l.x;
    #pragma unroll
    for (int i = 0; i < 4; i++) {
        __nv_bfloat16 bh = __float2bfloat16(m[i]);
        float f = m[i] - __bfloat162float(bh);
        hp[i] = __bfloat16_as_ushort(bh);
        lp[i] = __bfloat16_as_ushort(__float2bfloat16(f));
    }
    ((ushort4*)g_phi)[p] = h;
    ((ushort4*)g_plo)[p] = l;
}

// ---------------- 3) mask -> compacted active-key list ----------------------
__global__ void mask_kernel(const int* __restrict__ am) {
    __shared__ int sc[TP_];
    int b = blockIdx.x, tt = threadIdx.x;
    const int* m = am + b * T_ + tt * KP_;
    int s = m[0] + m[1] + m[2] + m[3];
    int act = (s == 0) ? 1 : 0;
    sc[tt] = act;
    __syncthreads();
    for (int off = 1; off < TP_; off <<= 1) {
        int v = 0;
        if (tt >= off) v = sc[tt - off];
        __syncthreads();
        sc[tt] += v;
        __syncthreads();
    }
    int total = sc[TP_ - 1];
    if (total == 0) {
        g_act[b * TP_ + tt] = tt;
        if (tt == 0) g_cnt[b] = TP_;
    } else {
        if (act) g_act[b * TP_ + sc[tt] - 1] = tt;
        if (tt >= total) g_act[b * TP_ + tt] = 0;
        if (tt == 0) g_cnt[b] = total;
    }
}

// ---------------- 4) mma.sync bf16x3 projection GEMM -------------------------
// C[M,N] = A[M,K] @ W[N,K]^T + bias, via (Ah+Al)(Wh+Wl) dropping Al*Wl.
// MODE 0: A = hs split, out g_Q [B,H,T,DH]. MODE 1: A = pooled gathered, out g_K/g_V.
//
// 128x128 CTA tile, 8 warps (warp_m = wid&3 -> 32 rows, warp_n = wid>>2 -> 64 cols).
// smem stage: 4 arrays (Ah, Al, Wh, Wl), each 128 rows x 32 bf16, row stride 40
// elements (80B) -> all ld.shared.b32 fragment reads are bank-conflict-free.
#define ARR_BYTES 10240              // 128 * 80
#define STAGE_BYTES (4 * ARR_BYTES)  // 40960
#define SMEM_GEMM (2 * STAGE_BYTES)  // 81920

template<int MODE>
__global__ void __launch_bounds__(256, 2)
gemm_mma_kernel(const float* __restrict__ bq_,
                const float* __restrict__ bk_, const float* __restrict__ bv_)
{
    extern __shared__ char smc[];
    const uint32_t sb = smem_u32(smc);
    const int tid = threadIdx.x;
    const int wid = tid >> 5, lane = tid & 31;
    const int bn = blockIdx.x * 128;
    const int bm = blockIdx.y * 128;

    const __nv_bfloat16 *Ah, *Al, *Wh, *Wl;
    const float* bias;
    float* outp;
    int batch = 0;
    if (MODE == 0) {
        Ah = g_hs_hi; Al = g_hs_lo; Wh = g_Wq_hi; Wl = g_Wq_lo;
        bias = bq_; outp = g_Q;
    } else {
        batch = blockIdx.z & 1;
        int sel = blockIdx.z >> 1;
        if (bm >= g_cnt[batch]) return;
        Ah = g_phi; Al = g_plo;
        Wh = sel ? g_Wv_hi : g_Wk_hi;
        Wl = sel ? g_Wv_lo : g_Wk_lo;
        bias = sel ? bv_ : bk_;
        outp = sel ? g_V : g_K;
    }

    // ---- stage loader: 2048 x 16B cp.async per stage ----
    auto load_stage = [&](int kt, int stage) {
        const uint32_t sbase = sb + stage * STAGE_BYTES;
        #pragma unroll
        for (int i = 0; i < 8; i++) {
            int idx = tid + i * 256;
            int a = idx >> 9;          // 0..3
            int r = (idx >> 2) & 127;  // row
            int c = idx & 3;           // 16B chunk
            uint32_t dst = sbase + a * ARR_BYTES + r * 80 + c * 16;
            const __nv_bfloat16* src;
            if (a < 2) {
                size_t row;
                if (MODE == 0) row = (size_t)(bm + r);
                else row = (size_t)batch * TP_ + g_act[batch * TP_ + bm + r];
                src = (a == 0 ? Ah : Al) + row * D_ + kt * 32 + c * 8;
            } else {
                src = (a == 2 ? Wh : Wl) + (size_t)(bn + r) * D_ + kt * 32 + c * 8;
            }
            CP_ASYNC16(dst, src);
        }
        CP_COMMIT();
    };

    float acc[2][8][4];
    #pragma unroll
    for (int mt = 0; mt < 2; mt++)
        #pragma unroll
        for (int nt = 0; nt < 8; nt++)
            #pragma unroll
            for (int j = 0; j < 4; j++) acc[mt][nt][j] = 0.0f;

    const int lr = lane >> 2;        // 0..7
    const int lc = (lane & 3) * 2;   // 0,2,4,6
    const int wm = (wid & 3) * 32;
    const int wn = (wid >> 2) * 64;

    const int NK = D_ / 32;          // 32 chunks
    load_stage(0, 0);

    for (int kt = 0; kt < NK; kt++) {
        if (kt + 1 < NK) {
            load_stage(kt + 1, (kt + 1) & 1);
            asm volatile("cp.async.wait_group 1;" ::: "memory");
        } else {
            asm volatile("cp.async.wait_group 0;" ::: "memory");
        }
        __syncthreads();

        const char* st = smc + (kt & 1) * STAGE_BYTES;
        const __nv_bfloat16* sAh = (const __nv_bfloat16*)(st);
        const __nv_bfloat16* sAl = (const __nv_bfloat16*)(st + ARR_BYTES);
        const __nv_bfloat16* sWh = (const __nv_bfloat16*)(st + 2 * ARR_BYTES);
        const __nv_bfloat16* sWl = (const __nv_bfloat16*)(st + 3 * ARR_BYTES);

        #pragma unroll
        for (int ks = 0; ks < 32; ks += 16) {
            uint32_t ahr[2][4], alr[2][4];
            #pragma unroll
            for (int mt = 0; mt < 2; mt++) {
                int r0 = wm + mt * 16 + lr;
                const __nv_bfloat16* pa = sAh + r0 * 40 + ks + lc;
                const __nv_bfloat16* pl = sAl + r0 * 40 + ks + lc;
                ahr[mt][0] = *(const uint32_t*)(pa);
                ahr[mt][1] = *(const uint32_t*)(pa + 8 * 40);
                ahr[mt][2] = *(const uint32_t*)(pa + 8);
                ahr[mt][3] = *(const uint32_t*)(pa + 8 * 40 + 8);
                alr[mt][0] = *(const uint32_t*)(pl);
                alr[mt][1] = *(const uint32_t*)(pl + 8 * 40);
                alr[mt][2] = *(const uint32_t*)(pl + 8);
                alr[mt][3] = *(const uint32_t*)(pl + 8 * 40 + 8);
            }
            #pragma unroll
            for (int nt = 0; nt < 8; nt++) {
                int rn = wn + nt * 8 + lr;
                const __nv_bfloat16* pbh = sWh + rn * 40 + ks + lc;
                const __nv_bfloat16* pbl = sWl + rn * 40 + ks + lc;
                uint32_t bh0 = *(const uint32_t*)(pbh);
                uint32_t bh1 = *(const uint32_t*)(pbh + 8);
                uint32_t bl0 = *(const uint32_t*)(pbl);
                uint32_t bl1 = *(const uint32_t*)(pbl + 8);
                #pragma unroll
                for (int mt = 0; mt < 2; mt++) {
                    mma_bf16(acc[mt][nt], ahr[mt][0], ahr[mt][1], ahr[mt][2], ahr[mt][3], bh0, bh1);
                    mma_bf16(acc[mt][nt], ahr[mt][0], ahr[mt][1], ahr[mt][2], ahr[mt][3], bl0, bl1);
                    mma_bf16(acc[mt][nt], alr[mt][0], alr[mt][1], alr[mt][2], alr[mt][3], bh0, bh1);
                }
            }
        }
        __syncthreads();
    }

    // ---- epilogue: + bias, head-major scatter ----
    #pragma unroll
    for (int nt = 0; nt < 8; nt++) {
        int n0 = bn + wn + nt * 8 + lc;
        int h = n0 >> 6, d0 = n0 & 63;
        float2 b2 = *(const float2*)(bias + n0);
        #pragma unroll
        for (int mt = 0; mt < 2; mt++) {
            int m0 = bm + wm + mt * 16 + lr;
            #pragma unroll
            for (int half = 0; half < 2; half++) {
                int m = m0 + half * 8;
                size_t dst;
                if (MODE == 0) {
                    int b = m >> 12, ls = m & (T_ - 1);
                    dst = ((size_t)(b * H_ + h) * T_ + ls) * DH_ + d0;
                } else {
                    dst = ((size_t)(batch * H_ + h) * TP_ + m) * DH_ + d0;
                }
                float2 o;
                o.x = acc[mt][nt][2 * half + 0] + b2.x;
                o.y = acc[mt][nt][2 * half + 1] + b2.y;
                *(float2*)(outp + dst) = o;
            }
        }
    }
}

// ---------------- 5) attention over compacted keys (fp32 SIMT) --------------
__global__ void __launch_bounds__(256)
attn_kernel(float* __restrict__ out)
{
    __shared__ float Qs[64][68];
    __shared__ float Kst[64][34];
    __shared__ float Vs[32][68];
    __shared__ float Ps[64][33];

    const int b = blockIdx.z, h = blockIdx.y, q0 = blockIdx.x * 64;
    const int tid = threadIdx.x;
    const int tx = tid & 15, ty = tid >> 4;
    const int cnt = g_cnt[b];
    const int ntiles = (cnt + 31) >> 5;

    const float* Qg = g_Q + ((size_t)(b * H_ + h) * T_ + q0) * DH_;
    const float* Kg = g_K + ((size_t)(b * H_ + h) * TP_) * DH_;
    const float* Vg = g_V + ((size_t)(b * H_ + h) * TP_) * DH_;

    for (int idx = tid; idx < 64 * 16; idx += 256) {
        int r = idx >> 4, c4 = (idx & 15) * 4;
        float4 v = *(const float4*)(Qg + (size_t)r * DH_ + c4);
        v.x *= 0.125f; v.y *= 0.125f; v.z *= 0.125f; v.w *= 0.125f;
        *(float4*)&Qs[r][c4] = v;
    }

    float acc[4][4];
    #pragma unroll
    for (int i = 0; i < 4; i++)
        #pragma unroll
        for (int j = 0; j < 4; j++) acc[i][j] = 0.0f;
    float mrow[4], lrow[4];
    #pragma unroll
    for (int i = 0; i < 4; i++) { mrow[i] = -1e30f; lrow[i] = 0.0f; }

    for (int t = 0; t < ntiles; t++) {
        const int kb = t * 32;
        __syncthreads();
        for (int idx = tid; idx < 512; idx += 256) {
            int c4 = idx >> 5, key = idx & 31;
            float4 v = *(const float4*)(Kg + (size_t)(kb + key) * DH_ + c4 * 4);
            Kst[c4 * 4 + 0][key] = v.x;
            Kst[c4 * 4 + 1][key] = v.y;
            Kst[c4 * 4 + 2][key] = v.z;
            Kst[c4 * 4 + 3][key] = v.w;
        }
        for (int idx = tid; idx < 512; idx += 256) {
            int r = idx >> 4, c4 = (idx & 15) * 4;
            *(float4*)&Vs[r][c4] = *(const float4*)(Vg + (size_t)(kb + r) * DH_ + c4);
        }
        __syncthreads();

        float s[4][2];
        #pragma unroll
        for (int i = 0; i < 4; i++) { s[i][0] = 0.0f; s[i][1] = 0.0f; }
        #pragma unroll
        for (int d = 0; d < 64; d++) {
            float2 bk2 = *(const float2*)&Kst[d][2 * tx];
            #pragma unroll
            for (int i = 0; i < 4; i++) {
                float a = Qs[4 * ty + i][d];
                s[i][0] = fmaf(a, bk2.x, s[i][0]);
                s[i][1] = fmaf(a, bk2.y, s[i][1]);
            }
        }
        #pragma unroll
        for (int j = 0; j < 2; j++)
            if (kb + 2 * tx + j >= cnt) {
                #pragma unroll
                for (int i = 0; i < 4; i++) s[i][j] = -1e30f;
            }

        #pragma unroll
        for (int i = 0; i < 4; i++) {
            float tm = fmaxf(s[i][0], s[i][1]);
            #pragma unroll
            for (int off = 8; off >= 1; off >>= 1)
                tm = fmaxf(tm, __shfl_xor_sync(0xffffffffu, tm, off));
            float mn = fmaxf(mrow[i], tm);
            float p0 = __expf(s[i][0] - mn);
            float p1 = __expf(s[i][1] - mn);
            Ps[4 * ty + i][2 * tx]     = p0;
            Ps[4 * ty + i][2 * tx + 1] = p1;
            float ts = p0 + p1;
            #pragma unroll
            for (int off = 8; off >= 1; off >>= 1)
                ts += __shfl_xor_sync(0xffffffffu, ts, off);
            float alpha = __expf(mrow[i] - mn);
            lrow[i] = lrow[i] * alpha + ts;
            mrow[i] = mn;
            #pragma unroll
            for (int j = 0; j < 4; j++) acc[i][j] *= alpha;
        }
        __syncwarp();

        #pragma unroll
        for (int kk = 0; kk < 32; kk++) {
            float v4[4];
            *(float4*)v4 = *(const float4*)&Vs[kk][4 * tx];
            #pragma unroll
            for (int i = 0; i < 4; i++) {
                float p = Ps[4 * ty + i][kk];
                #pragma unroll
                for (int j = 0; j < 4; j++)
                    acc[i][j] = fmaf(p, v4[j], acc[i][j]);
            }
        }
    }

    #pragma unroll
    for (int i = 0; i < 4; i++) {
        int row = 4 * ty + i;
        float inv = 1.0f / lrow[i];
        float4 r;
        r.x = acc[i][0] * inv; r.y = acc[i][1] * inv;
        r.z = acc[i][2] * inv; r.w = acc[i][3] * inv;
        *(float4*)(out + ((size_t)(b * T_ + q0 + row)) * D_ + h * DH_ + 4 * tx) = r;
    }
}

// ---------------- launch -----------------------------------------------------
extern "C" void kernel_launch(void* const* d_in, const int* in_sizes, int n_in,
                              void* d_out, int out_size) {
    const float* hs = (const float*)d_in[0];
    const int*   am = (const int*)d_in[1];
    const float* Wq = (const float*)d_in[2];
    const float* bq = (const float*)d_in[3];
    const float* Wk = (const float*)d_in[4];
    const float* bk = (const float*)d_in[5];
    const float* Wv = (const float*)d_in[6];
    const float* bv = (const float*)d_in[7];
    float* out = (float*)d_out;

    cudaFuncSetAttribute(gemm_mma_kernel<0>, cudaFuncAttributeMaxDynamicSharedMemorySize, SMEM_GEMM);
    cudaFuncSetAttribute(gemm_mma_kernel<1>, cudaFuncAttributeMaxDynamicSharedMemorySize, SMEM_GEMM);

    __nv_bfloat16 *hs_hi, *hs_lo, *wq_hi, *wq_lo, *wk_hi, *wk_lo, *wv_hi, *wv_lo;
    cudaGetSymbolAddress((void**)&hs_hi, g_hs_hi);
    cudaGetSymbolAddress((void**)&hs_lo, g_hs_lo);
    cudaGetSymbolAddress((void**)&wq_hi, g_Wq_hi);
    cudaGetSymbolAddress((void**)&wq_lo, g_Wq_lo);
    cudaGetSymbolAddress((void**)&wk_hi, g_Wk_hi);
    cudaGetSymbolAddress((void**)&wk_lo, g_Wk_lo);
    cudaGetSymbolAddress((void**)&wv_hi, g_Wv_hi);
    cudaGetSymbolAddress((void**)&wv_lo, g_Wv_lo);

    int n4_hs = B_ * T_ * D_ / 4;
    int n4_w  = D_ * D_ / 4;
    split_kernel<<<(n4_hs + 255) / 256, 256>>>(hs, hs_hi, hs_lo, n4_hs);
    split_kernel<<<(n4_w + 255) / 256, 256>>>(Wq, wq_hi, wq_lo, n4_w);
    split_kernel<<<(n4_w + 255) / 256, 256>>>(Wk, wk_hi, wk_lo, n4_w);
    split_kernel<<<(n4_w + 255) / 256, 256>>>(Wv, wv_hi, wv_lo, n4_w);
    pool_split_kernel<<<(B_ * TP_ * D_ / 4) / 256, 256>>>(hs);
    mask_kernel<<<B_, TP_>>>(am);
    gemm_mma_kernel<0><<<dim3(D_ / 128, (B_ * T_) / 128, 1), 256, SMEM_GEMM>>>(bq, nullptr, nullptr);
    gemm_mma_kernel<1><<<dim3(D_ / 128, TP_ / 128, 2 * B_), 256, SMEM_GEMM>>>(nullptr, bk, bv);
    attn_kernel<<<dim3(T_ / 64, H_, B_), 256>>>(out);
}

// round 4
// speedup vs baseline: 2.0349x; 1.0470x over previous
#include <cuda_runtime.h>
#include <cuda_bf16.h>
#include <cstdint>

#define B_  2
#define T_  4096
#define D_  1024
#define H_  16
#define DH_ 64
#define KP_ 4
#define TP_ 1024

// ---------------- scratch (device globals; no allocations allowed) ----------
__device__ __nv_bfloat16 g_hs_hi[(size_t)B_ * T_ * D_];
__device__ __nv_bfloat16 g_hs_lo[(size_t)B_ * T_ * D_];
__device__ __nv_bfloat16 g_phi[B_ * TP_ * D_];
__device__ __nv_bfloat16 g_plo[B_ * TP_ * D_];
__device__ __nv_bfloat16 g_Wq_hi[D_ * D_], g_Wq_lo[D_ * D_];
__device__ __nv_bfloat16 g_Wk_hi[D_ * D_], g_Wk_lo[D_ * D_];
__device__ __nv_bfloat16 g_Wv_hi[D_ * D_], g_Wv_lo[D_ * D_];
__device__ float g_Q[(size_t)B_ * H_ * T_ * DH_];   // [B,H,T,DH]
__device__ float g_K[(size_t)B_ * H_ * TP_ * DH_];  // [B,H,TP,DH] compacted
__device__ float g_V[(size_t)B_ * H_ * TP_ * DH_];
__device__ int   g_act[B_ * TP_];
__device__ int   g_cnt[B_];

// ---------------- helpers ----------------------------------------------------
__device__ __forceinline__ uint32_t smem_u32(const void* p) {
    uint32_t a;
    asm("{ .reg .u64 t; cvta.to.shared.u64 t, %1; cvt.u32.u64 %0, t; }" : "=r"(a) : "l"(p));
    return a;
}
#define CP_ASYNC16(dst, src) \
    asm volatile("cp.async.cg.shared.global [%0], [%1], 16;" :: "r"(dst), "l"(src))
#define CP_COMMIT() asm volatile("cp.async.commit_group;" ::: "memory")

__device__ __forceinline__ void mma_bf16(float* c,
        uint32_t a0, uint32_t a1, uint32_t a2, uint32_t a3,
        uint32_t b0, uint32_t b1) {
    asm volatile("mma.sync.aligned.m16n8k16.row.col.f32.bf16.bf16.f32 "
        "{%0,%1,%2,%3}, {%4,%5,%6,%7}, {%8,%9}, {%0,%1,%2,%3};"
        : "+f"(c[0]), "+f"(c[1]), "+f"(c[2]), "+f"(c[3])
        : "r"(a0), "r"(a1), "r"(a2), "r"(a3), "r"(b0), "r"(b1));
}
__device__ __forceinline__ void ldsm_x4(uint32_t* r, uint32_t addr) {
    asm volatile("ldmatrix.sync.aligned.m8n8.x4.shared.b16 {%0,%1,%2,%3}, [%4];"
        : "=r"(r[0]), "=r"(r[1]), "=r"(r[2]), "=r"(r[3]) : "r"(addr));
}
__device__ __forceinline__ void split1(float v, unsigned short& h, unsigned short& l) {
    __nv_bfloat16 bh = __float2bfloat16(v);
    float f = v - __bfloat162float(bh);
    h = __bfloat16_as_ushort(bh);
    l = __bfloat16_as_ushort(__float2bfloat16(f));
}

// ---------------- 1) weight splits (Wq, Wk, Wv in one launch) ----------------
#define W4_ (D_ * D_ / 4)
__global__ void wsplit_kernel(const float* __restrict__ Wq,
                              const float* __restrict__ Wk,
                              const float* __restrict__ Wv) {
    int p = blockIdx.x * blockDim.x + threadIdx.x;
    const float* src;
    __nv_bfloat16 *hi, *lo;
    int seg = p / W4_, off = p - seg * W4_;
    if (seg == 0)      { src = Wq; hi = g_Wq_hi; lo = g_Wq_lo; }
    else if (seg == 1) { src = Wk; hi = g_Wk_hi; lo = g_Wk_lo; }
    else               { src = Wv; hi = g_Wv_hi; lo = g_Wv_lo; }
    float4 v = ((const float4*)src)[off];
    ushort4 h, l;
    split1(v.x, h.x, l.x); split1(v.y, h.y, l.y);
    split1(v.z, h.z, l.z); split1(v.w, h.w, l.w);
    ((ushort4*)hi)[off] = h;
    ((ushort4*)lo)[off] = l;
}

// ---------------- 2) hs split + avgpool + pooled split (single hs pass) -----
__global__ void hs_pool_split_kernel(const float* __restrict__ hs) {
    int p = blockIdx.x * blockDim.x + threadIdx.x;   // (b, tt, d4) over pooled
    int d4  = p & 255;
    int row = p >> 8;            // [0, B*TP)
    const float4* src = (const float4*)hs;
    size_t base = (size_t)row * (KP_ * 256) + d4;    // hs float4 index of row tt*KP
    float4 s[4];
    #pragma unroll
    for (int r = 0; r < 4; r++) s[r] = src[base + r * 256];
    // write hs hi/lo for the 4 rows
    #pragma unroll
    for (int r = 0; r < 4; r++) {
        ushort4 h, l;
        split1(s[r].x, h.x, l.x); split1(s[r].y, h.y, l.y);
        split1(s[r].z, h.z, l.z); split1(s[r].w, h.w, l.w);
        ((ushort4*)g_hs_hi)[base + r * 256] = h;
        ((ushort4*)g_hs_lo)[base + r * 256] = l;
    }
    // pooled mean + split
    float m[4];
    m[0] = (s[0].x + s[1].x + s[2].x + s[3].x) * 0.25f;
    m[1] = (s[0].y + s[1].y + s[2].y + s[3].y) * 0.25f;
    m[2] = (s[0].z + s[1].z + s[2].z + s[3].z) * 0.25f;
    m[3] = (s[0].w + s[1].w + s[2].w + s[3].w) * 0.25f;
    ushort4 h, l;
    split1(m[0], h.x, l.x); split1(m[1], h.y, l.y);
    split1(m[2], h.z, l.z); split1(m[3], h.w, l.w);
    ((ushort4*)g_phi)[p] = h;
    ((ushort4*)g_plo)[p] = l;
}

// ---------------- 3) mask -> compacted active-key list ----------------------
__global__ void mask_kernel(const int* __restrict__ am) {
    __shared__ int sc[TP_];
    int b = blockIdx.x, tt = threadIdx.x;
    const int* m = am + b * T_ + tt * KP_;
    int s = m[0] + m[1] + m[2] + m[3];
    int act = (s == 0) ? 1 : 0;
    sc[tt] = act;
    __syncthreads();
    for (int off = 1; off < TP_; off <<= 1) {
        int v = 0;
        if (tt >= off) v = sc[tt - off];
        __syncthreads();
        sc[tt] += v;
        __syncthreads();
    }
    int total = sc[TP_ - 1];
    if (total == 0) {
        g_act[b * TP_ + tt] = tt;
        if (tt == 0) g_cnt[b] = TP_;
    } else {
        if (act) g_act[b * TP_ + sc[tt] - 1] = tt;
        if (tt >= total) g_act[b * TP_ + tt] = 0;
        if (tt == 0) g_cnt[b] = total;
    }
}

// ---------------- 4) mma.sync bf16x3 projection GEMM -------------------------
// C[M,N] = A[M,K] @ W[N,K]^T + bias via (Ah+Al)(Wh+Wl), dropping Al*Wl.
// 128x128 CTA tile, 8 warps (warp 32x64), ldmatrix fragments, 80B row stride
// (bank-conflict-free for ldmatrix 8-row phases), 2-stage cp.async.
#define RS_ 80                       // smem row stride, bytes
#define ARR_BYTES (128 * RS_)        // 10240
#define STAGE_BYTES (4 * ARR_BYTES)  // 40960
#define SMEM_GEMM (2 * STAGE_BYTES)  // 81920

template<int MODE>
__global__ void __launch_bounds__(256, 2)
gemm_mma_kernel(const float* __restrict__ bq_,
                const float* __restrict__ bk_, const float* __restrict__ bv_)
{
    extern __shared__ char smc[];
    const uint32_t sb = smem_u32(smc);
    const int tid = threadIdx.x;
    const int wid = tid >> 5, lane = tid & 31;
    const int bn = blockIdx.x * 128;
    const int bm = blockIdx.y * 128;

    const __nv_bfloat16 *Ah, *Al, *Wh, *Wl;
    const float* bias;
    float* outp;
    int batch = 0;
    if (MODE == 0) {
        Ah = g_hs_hi; Al = g_hs_lo; Wh = g_Wq_hi; Wl = g_Wq_lo;
        bias = bq_; outp = g_Q;
    } else {
        batch = blockIdx.z & 1;
        int sel = blockIdx.z >> 1;
        if (bm >= g_cnt[batch]) return;
        Ah = g_phi; Al = g_plo;
        Wh = sel ? g_Wv_hi : g_Wk_hi;
        Wl = sel ? g_Wv_lo : g_Wk_lo;
        bias = sel ? bv_ : bk_;
        outp = sel ? g_V : g_K;
    }

    // ---- stage loader: 2048 x 16B cp.async per stage ----
    auto load_stage = [&](int kt, int stage) {
        const uint32_t sbase = sb + stage * STAGE_BYTES;
        #pragma unroll
        for (int i = 0; i < 8; i++) {
            int idx = tid + i * 256;
            int a = idx >> 9;          // array 0..3
            int r = (idx >> 2) & 127;  // row
            int c = idx & 3;           // 16B chunk
            uint32_t dst = sbase + a * ARR_BYTES + r * RS_ + c * 16;
            const __nv_bfloat16* src;
            if (a < 2) {
                size_t row;
                if (MODE == 0) row = (size_t)(bm + r);
                else row = (size_t)batch * TP_ + g_act[batch * TP_ + bm + r];
                src = (a == 0 ? Ah : Al) + row * D_ + kt * 32 + c * 8;
            } else {
                src = (a == 2 ? Wh : Wl) + (size_t)(bn + r) * D_ + kt * 32 + c * 8;
            }
            CP_ASYNC16(dst, src);
        }
        CP_COMMIT();
    };

    float acc[2][8][4];
    #pragma unroll
    for (int mt = 0; mt < 2; mt++)
        #pragma unroll
        for (int nt = 0; nt < 8; nt++)
            #pragma unroll
            for (int j = 0; j < 4; j++) acc[mt][nt][j] = 0.0f;

    const int wm = (wid & 3) * 32;
    const int wn = (wid >> 2) * 64;

    // ldmatrix per-lane base offsets
    const int arow = (lane & 7) + ((lane >> 3) & 1) * 8;  // A: row-in-16, kh = lane>>4
    const int akh  = lane >> 4;
    const int brow = (lane & 7) + (lane >> 4) * 8;        // B: n-in-16,  kh = (lane>>3)&1
    const int bkh  = (lane >> 3) & 1;
    const uint32_t aoff = (uint32_t)((wm + arow) * RS_ + akh * 16);
    const uint32_t boff = (uint32_t)(2 * ARR_BYTES + (wn + brow) * RS_ + bkh * 16);

    const int NK = D_ / 32;
    load_stage(0, 0);

    for (int kt = 0; kt < NK; kt++) {
        if (kt + 1 < NK) {
            load_stage(kt + 1, (kt + 1) & 1);
            asm volatile("cp.async.wait_group 1;" ::: "memory");
        } else {
            asm volatile("cp.async.wait_group 0;" ::: "memory");
        }
        __syncthreads();

        const uint32_t st = sb + (kt & 1) * STAGE_BYTES;
        const uint32_t aB = st + aoff;
        const uint32_t bB = st + boff;

        #pragma unroll
        for (int ks = 0; ks < 2; ks++) {    // two k16 halves of the 32-chunk
            const uint32_t ko = ks * 32;    // 16 elems = 32 bytes
            uint32_t ah[2][4], al[2][4];
            ldsm_x4(ah[0], aB + ko);
            ldsm_x4(ah[1], aB + 16 * RS_ + ko);
            ldsm_x4(al[0], aB + ARR_BYTES + ko);
            ldsm_x4(al[1], aB + ARR_BYTES + 16 * RS_ + ko);
            #pragma unroll
            for (int np = 0; np < 4; np++) {
                uint32_t bh[4], bl[4];
                ldsm_x4(bh, bB + np * 16 * RS_ + ko);
                ldsm_x4(bl, bB + ARR_BYTES + np * 16 * RS_ + ko);
                #pragma unroll
                for (int s = 0; s < 2; s++) {
                    const int nt = 2 * np + s;
                    #pragma unroll
                    for (int mt = 0; mt < 2; mt++) {
                        mma_bf16(acc[mt][nt], ah[mt][0], ah[mt][1], ah[mt][2], ah[mt][3], bh[2*s], bh[2*s+1]);
                        mma_bf16(acc[mt][nt], ah[mt][0], ah[mt][1], ah[mt][2], ah[mt][3], bl[2*s], bl[2*s+1]);
                        mma_bf16(acc[mt][nt], al[mt][0], al[mt][1], al[mt][2], al[mt][3], bh[2*s], bh[2*s+1]);
                    }
                }
            }
        }
        __syncthreads();
    }

    // ---- epilogue: + bias, head-major scatter ----
    const int lr = lane >> 2;
    const int lc = (lane & 3) * 2;
    #pragma unroll
    for (int nt = 0; nt < 8; nt++) {
        // nt tile n-offset: np=nt/2 pair base + (nt&1)*8
        int n0 = bn + wn + (nt >> 1) * 16 + (nt & 1) * 8 + lc;
        int h = n0 >> 6, d0 = n0 & 63;
        float2 b2 = *(const float2*)(bias + n0);
        #pragma unroll
        for (int mt = 0; mt < 2; mt++) {
            int m0 = bm + wm + mt * 16 + lr;
            #pragma unroll
            for (int half = 0; half < 2; half++) {
                int m = m0 + half * 8;
                size_t dst;
                if (MODE == 0) {
                    int b = m >> 12, ls = m & (T_ - 1);
                    dst = ((size_t)(b * H_ + h) * T_ + ls) * DH_ + d0;
                } else {
                    dst = ((size_t)(batch * H_ + h) * TP_ + m) * DH_ + d0;
                }
                float2 o;
                o.x = acc[mt][nt][2 * half + 0] + b2.x;
                o.y = acc[mt][nt][2 * half + 1] + b2.y;
                *(float2*)(outp + dst) = o;
            }
        }
    }
}

// ---------------- 5) attention over compacted keys (fp32 SIMT) --------------
__global__ void __launch_bounds__(256)
attn_kernel(float* __restrict__ out)
{
    __shared__ float Qs[64][68];
    __shared__ float Kst[64][34];
    __shared__ float Vs[32][68];
    __shared__ float Ps[64][33];

    const int b = blockIdx.z, h = blockIdx.y, q0 = blockIdx.x * 64;
    const int tid = threadIdx.x;
    const int tx = tid & 15, ty = tid >> 4;
    const int cnt = g_cnt[b];
    const int ntiles = (cnt + 31) >> 5;

    const float* Qg = g_Q + ((size_t)(b * H_ + h) * T_ + q0) * DH_;
    const float* Kg = g_K + ((size_t)(b * H_ + h) * TP_) * DH_;
    const float* Vg = g_V + ((size_t)(b * H_ + h) * TP_) * DH_;

    for (int idx = tid; idx < 64 * 16; idx += 256) {
        int r = idx >> 4, c4 = (idx & 15) * 4;
        float4 v = *(const float4*)(Qg + (size_t)r * DH_ + c4);
        v.x *= 0.125f; v.y *= 0.125f; v.z *= 0.125f; v.w *= 0.125f;
        *(float4*)&Qs[r][c4] = v;
    }

    float acc[4][4];
    #pragma unroll
    for (int i = 0; i < 4; i++)
        #pragma unroll
        for (int j = 0; j < 4; j++) acc[i][j] = 0.0f;
    float mrow[4], lrow[4];
    #pragma unroll
    for (int i = 0; i < 4; i++) { mrow[i] = -1e30f; lrow[i] = 0.0f; }

    for (int t = 0; t < ntiles; t++) {
        const int kb = t * 32;
        __syncthreads();
        for (int idx = tid; idx < 512; idx += 256) {
            int c4 = idx >> 5, key = idx & 31;
            float4 v = *(const float4*)(Kg + (size_t)(kb + key) * DH_ + c4 * 4);
            Kst[c4 * 4 + 0][key] = v.x;
            Kst[c4 * 4 + 1][key] = v.y;
            Kst[c4 * 4 + 2][key] = v.z;
            Kst[c4 * 4 + 3][key] = v.w;
        }
        for (int idx = tid; idx < 512; idx += 256) {
            int r = idx >> 4, c4 = (idx & 15) * 4;
            *(float4*)&Vs[r][c4] = *(const float4*)(Vg + (size_t)(kb + r) * DH_ + c4);
        }
        __syncthreads();

        float s[4][2];
        #pragma unroll
        for (int i = 0; i < 4; i++) { s[i][0] = 0.0f; s[i][1] = 0.0f; }
        #pragma unroll
        for (int d = 0; d < 64; d++) {
            float2 bk2 = *(const float2*)&Kst[d][2 * tx];
            #pragma unroll
            for (int i = 0; i < 4; i++) {
                float a = Qs[4 * ty + i][d];
                s[i][0] = fmaf(a, bk2.x, s[i][0]);
                s[i][1] = fmaf(a, bk2.y, s[i][1]);
            }
        }
        #pragma unroll
        for (int j = 0; j < 2; j++)
            if (kb + 2 * tx + j >= cnt) {
                #pragma unroll
                for (int i = 0; i < 4; i++) s[i][j] = -1e30f;
            }

        #pragma unroll
        for (int i = 0; i < 4; i++) {
            float tm = fmaxf(s[i][0], s[i][1]);
            #pragma unroll
            for (int off = 8; off >= 1; off >>= 1)
                tm = fmaxf(tm, __shfl_xor_sync(0xffffffffu, tm, off));
            float mn = fmaxf(mrow[i], tm);
            float p0 = __expf(s[i][0] - mn);
            float p1 = __expf(s[i][1] - mn);
            Ps[4 * ty + i][2 * tx]     = p0;
            Ps[4 * ty + i][2 * tx + 1] = p1;
            float ts = p0 + p1;
            #pragma unroll
            for (int off = 8; off >= 1; off >>= 1)
                ts += __shfl_xor_sync(0xffffffffu, ts, off);
            float alpha = __expf(mrow[i] - mn);
            lrow[i] = lrow[i] * alpha + ts;
            mrow[i] = mn;
            #pragma unroll
            for (int j = 0; j < 4; j++) acc[i][j] *= alpha;
        }
        __syncwarp();

        #pragma unroll
        for (int kk = 0; kk < 32; kk++) {
            float v4[4];
            *(float4*)v4 = *(const float4*)&Vs[kk][4 * tx];
            #pragma unroll
            for (int i = 0; i < 4; i++) {
                float p = Ps[4 * ty + i][kk];
                #pragma unroll
                for (int j = 0; j < 4; j++)
                    acc[i][j] = fmaf(p, v4[j], acc[i][j]);
            }
        }
    }

    #pragma unroll
    for (int i = 0; i < 4; i++) {
        int row = 4 * ty + i;
        float inv = 1.0f / lrow[i];
        float4 r;
        r.x = acc[i][0] * inv; r.y = acc[i][1] * inv;
        r.z = acc[i][2] * inv; r.w = acc[i][3] * inv;
        *(float4*)(out + ((size_t)(b * T_ + q0 + row)) * D_ + h * DH_ + 4 * tx) = r;
    }
}

// ---------------- launch -----------------------------------------------------
extern "C" void kernel_launch(void* const* d_in, const int* in_sizes, int n_in,
                              void* d_out, int out_size) {
    const float* hs = (const float*)d_in[0];
    const int*   am = (const int*)d_in[1];
    const float* Wq = (const float*)d_in[2];
    const float* bq = (const float*)d_in[3];
    const float* Wk = (const float*)d_in[4];
    const float* bk = (const float*)d_in[5];
    const float* Wv = (const float*)d_in[6];
    const float* bv = (const float*)d_in[7];
    float* out = (float*)d_out;

    cudaFuncSetAttribute(gemm_mma_kernel<0>, cudaFuncAttributeMaxDynamicSharedMemorySize, SMEM_GEMM);
    cudaFuncSetAttribute(gemm_mma_kernel<1>, cudaFuncAttributeMaxDynamicSharedMemorySize, SMEM_GEMM);

    wsplit_kernel<<<3 * W4_ / 256, 256>>>(Wq, Wk, Wv);
    hs_pool_split_kernel<<<(B_ * TP_ * D_ / 4) / 256, 256>>>(hs);
    mask_kernel<<<B_, TP_>>>(am);
    gemm_mma_kernel<0><<<dim3(D_ / 128, (B_ * T_) / 128, 1), 256, SMEM_GEMM>>>(bq, nullptr, nullptr);
    gemm_mma_kernel<1><<<dim3(D_ / 128, TP_ / 128, 2 * B_), 256, SMEM_GEMM>>>(nullptr, bk, bv);
    attn_kernel<<<dim3(T_ / 64, H_, B_), 256>>>(out);
}

// round 7
// speedup vs baseline: 2.0448x; 1.0048x over previous
#include <cuda_runtime.h>
#include <cuda_bf16.h>
#include <cstdint>

#define B_  2
#define T_  4096
#define D_  1024
#define H_  16
#define DH_ 64
#define KP_ 4
#define TP_ 1024

// ---------------- scratch (device globals; no allocations allowed) ----------
__device__ __nv_bfloat16 g_hs_hi[(size_t)B_ * T_ * D_];
__device__ __nv_bfloat16 g_hs_lo[(size_t)B_ * T_ * D_];
__device__ __nv_bfloat16 g_phi[B_ * TP_ * D_];
__device__ __nv_bfloat16 g_plo[B_ * TP_ * D_];
__device__ __nv_bfloat16 g_Wq_hi[D_ * D_], g_Wq_lo[D_ * D_];
__device__ __nv_bfloat16 g_Wk_hi[D_ * D_], g_Wk_lo[D_ * D_];
__device__ __nv_bfloat16 g_Wv_hi[D_ * D_], g_Wv_lo[D_ * D_];
__device__ float g_Q[(size_t)B_ * H_ * T_ * DH_];   // [B,H,T,DH]
__device__ float g_K[(size_t)B_ * H_ * TP_ * DH_];  // [B,H,TP,DH] compacted
__device__ float g_V[(size_t)B_ * H_ * TP_ * DH_];
__device__ int   g_act[B_ * TP_];
__device__ int   g_cnt[B_];

// ---------------- helpers ----------------------------------------------------
__device__ __forceinline__ uint32_t smem_u32(const void* p) {
    uint32_t a;
    asm("{ .reg .u64 t; cvta.to.shared.u64 t, %1; cvt.u32.u64 %0, t; }" : "=r"(a) : "l"(p));
    return a;
}
#define CP_ASYNC16(dst, src) \
    asm volatile("cp.async.cg.shared.global [%0], [%1], 16;" :: "r"(dst), "l"(src))
#define CP_COMMIT() asm volatile("cp.async.commit_group;" ::: "memory")

__device__ __forceinline__ void mma_bf16(float* c,
        uint32_t a0, uint32_t a1, uint32_t a2, uint32_t a3,
        uint32_t b0, uint32_t b1) {
    asm volatile("mma.sync.aligned.m16n8k16.row.col.f32.bf16.bf16.f32 "
        "{%0,%1,%2,%3}, {%4,%5,%6,%7}, {%8,%9}, {%0,%1,%2,%3};"
        : "+f"(c[0]), "+f"(c[1]), "+f"(c[2]), "+f"(c[3])
        : "r"(a0), "r"(a1), "r"(a2), "r"(a3), "r"(b0), "r"(b1));
}
__device__ __forceinline__ void ldsm_x4(uint32_t* r, uint32_t addr) {
    asm volatile("ldmatrix.sync.aligned.m8n8.x4.shared.b16 {%0,%1,%2,%3}, [%4];"
        : "=r"(r[0]), "=r"(r[1]), "=r"(r[2]), "=r"(r[3]) : "r"(addr));
}
__device__ __forceinline__ void split1(float v, unsigned short& h, unsigned short& l) {
    __nv_bfloat16 bh = __float2bfloat16(v);
    float f = v - __bfloat162float(bh);
    h = __bfloat16_as_ushort(bh);
    l = __bfloat16_as_ushort(__float2bfloat16(f));
}

// ---------------- 1) weight splits (Wq, Wk, Wv in one launch) ----------------
#define W4_ (D_ * D_ / 4)
__global__ void wsplit_kernel(const float* __restrict__ Wq,
                              const float* __restrict__ Wk,
                              const float* __restrict__ Wv) {
    int p = blockIdx.x * blockDim.x + threadIdx.x;
    const float* src;
    __nv_bfloat16 *hi, *lo;
    int seg = p / W4_, off = p - seg * W4_;
    if (seg == 0)      { src = Wq; hi = g_Wq_hi; lo = g_Wq_lo; }
    else if (seg == 1) { src = Wk; hi = g_Wk_hi; lo = g_Wk_lo; }
    else               { src = Wv; hi = g_Wv_hi; lo = g_Wv_lo; }
    float4 v = ((const float4*)src)[off];
    ushort4 h, l;
    split1(v.x, h.x, l.x); split1(v.y, h.y, l.y);
    split1(v.z, h.z, l.z); split1(v.w, h.w, l.w);
    ((ushort4*)hi)[off] = h;
    ((ushort4*)lo)[off] = l;
}

// ---------------- 2) hs split + avgpool + pooled split (single hs pass) -----
__global__ void hs_pool_split_kernel(const float* __restrict__ hs) {
    int p = blockIdx.x * blockDim.x + threadIdx.x;
    int d4  = p & 255;
    int row = p >> 8;
    const float4* src = (const float4*)hs;
    size_t base = (size_t)row * (KP_ * 256) + d4;
    float4 s[4];
    #pragma unroll
    for (int r = 0; r < 4; r++) s[r] = src[base + r * 256];
    #pragma unroll
    for (int r = 0; r < 4; r++) {
        ushort4 h, l;
        split1(s[r].x, h.x, l.x); split1(s[r].y, h.y, l.y);
        split1(s[r].z, h.z, l.z); split1(s[r].w, h.w, l.w);
        ((ushort4*)g_hs_hi)[base + r * 256] = h;
        ((ushort4*)g_hs_lo)[base + r * 256] = l;
    }
    float m[4];
    m[0] = (s[0].x + s[1].x + s[2].x + s[3].x) * 0.25f;
    m[1] = (s[0].y + s[1].y + s[2].y + s[3].y) * 0.25f;
    m[2] = (s[0].z + s[1].z + s[2].z + s[3].z) * 0.25f;
    m[3] = (s[0].w + s[1].w + s[2].w + s[3].w) * 0.25f;
    ushort4 h, l;
    split1(m[0], h.x, l.x); split1(m[1], h.y, l.y);
    split1(m[2], h.z, l.z); split1(m[3], h.w, l.w);
    ((ushort4*)g_phi)[p] = h;
    ((ushort4*)g_plo)[p] = l;
}

// ---------------- 3) mask -> compacted active-key list ----------------------
__global__ void mask_kernel(const int* __restrict__ am) {
    __shared__ int sc[TP_];
    int b = blockIdx.x, tt = threadIdx.x;
    const int* m = am + b * T_ + tt * KP_;
    int s = m[0] + m[1] + m[2] + m[3];
    int act = (s == 0) ? 1 : 0;
    sc[tt] = act;
    __syncthreads();
    for (int off = 1; off < TP_; off <<= 1) {
        int v = 0;
        if (tt >= off) v = sc[tt - off];
        __syncthreads();
        sc[tt] += v;
        __syncthreads();
    }
    int total = sc[TP_ - 1];
    if (total == 0) {
        g_act[b * TP_ + tt] = tt;
        if (tt == 0) g_cnt[b] = TP_;
    } else {
        if (act) g_act[b * TP_ + sc[tt] - 1] = tt;
        if (tt >= total) g_act[b * TP_ + tt] = 0;
        if (tt == 0) g_cnt[b] = total;
    }
}

// ---------------- 4) mma.sync bf16x3 projection GEMM -------------------------
// C[M,N] = A[M,K] @ W[N,K]^T + bias via (Ah+Al)(Wh+Wl), dropping Al*Wl.
// 128x128 CTA tile, 8 warps (warp 32x64), ldmatrix fragments.
// 4-stage cp.async pipeline, one k16 chunk per stage, ONE __syncthreads/iter.
// Row stride 48B: 16B-aligned (ldmatrix requirement!) and conflict-free
// (8-row phases hit banks 12r mod 32 = {0,12,24,4,16,28,8,20}, all distinct).
#define RS_ 48                       // smem row stride, bytes (16 bf16 payload)
#define ARR_BYTES (128 * RS_)        // 6144
#define STAGE_BYTES (4 * ARR_BYTES)  // 24576
#define NSTAGE 4
#define SMEM_GEMM (NSTAGE * STAGE_BYTES)  // 98304

template<int MODE>
__global__ void __launch_bounds__(256, 2)
gemm_mma_kernel(const float* __restrict__ bq_,
                const float* __restrict__ bk_, const float* __restrict__ bv_)
{
    extern __shared__ char smc[];
    const uint32_t sb = smem_u32(smc);
    const int tid = threadIdx.x;
    const int wid = tid >> 5, lane = tid & 31;
    const int bn = blockIdx.x * 128;
    const int bm = blockIdx.y * 128;

    const __nv_bfloat16 *Ah, *Al, *Wh, *Wl;
    const float* bias;
    float* outp;
    int batch = 0;
    if (MODE == 0) {
        Ah = g_hs_hi; Al = g_hs_lo; Wh = g_Wq_hi; Wl = g_Wq_lo;
        bias = bq_; outp = g_Q;
    } else {
        batch = blockIdx.z & 1;
        int sel = blockIdx.z >> 1;
        if (bm >= g_cnt[batch]) return;
        Ah = g_phi; Al = g_plo;
        Wh = sel ? g_Wv_hi : g_Wk_hi;
        Wl = sel ? g_Wv_lo : g_Wk_lo;
        bias = sel ? bv_ : bk_;
        outp = sel ? g_V : g_K;
    }

    // per-thread load assignment: 1024 cp.async16 per stage, 4 per thread
    const __nv_bfloat16* srcb[4];
    {
        int r0 = (tid >> 1) & 127;
        size_t arow;
        if (MODE == 0) arow = (size_t)(bm + r0);
        else arow = (size_t)batch * TP_ + g_act[batch * TP_ + bm + r0];
        size_t wrow = (size_t)(bn + r0);
        srcb[0] = Ah + arow * D_;
        srcb[1] = Al + arow * D_;
        srcb[2] = Wh + wrow * D_;
        srcb[3] = Wl + wrow * D_;
    }
    const int lc16 = (tid & 1) * 8;  // element offset of 16B chunk within k16

    auto load_stage = [&](int kt, int stage) {
        const uint32_t sbase = sb + stage * STAGE_BYTES;
        const uint32_t dbase = sbase + (((tid >> 1) & 127) * RS_) + (tid & 1) * 16;
        const int koff = kt * 16 + lc16;
        #pragma unroll
        for (int a = 0; a < 4; a++)
            CP_ASYNC16(dbase + a * ARR_BYTES, srcb[a] + koff);
    };

    float acc[2][8][4];
    #pragma unroll
    for (int mt = 0; mt < 2; mt++)
        #pragma unroll
        for (int nt = 0; nt < 8; nt++)
            #pragma unroll
            for (int j = 0; j < 4; j++) acc[mt][nt][j] = 0.0f;

    const int wm = (wid & 3) * 32;
    const int wn = (wid >> 2) * 64;

    // ldmatrix per-lane base offsets
    const int arow = (lane & 7) + ((lane >> 3) & 1) * 8;
    const int akh  = lane >> 4;
    const int brow = (lane & 7) + (lane >> 4) * 8;
    const int bkh  = (lane >> 3) & 1;
    const uint32_t aoff = (uint32_t)((wm + arow) * RS_ + akh * 16);
    const uint32_t boff = (uint32_t)(2 * ARR_BYTES + (wn + brow) * RS_ + bkh * 16);

    const int NK = D_ / 16;   // 64 k16 chunks

    // prologue: 3 stages in flight
    #pragma unroll
    for (int s = 0; s < NSTAGE - 1; s++) { load_stage(s, s); CP_COMMIT(); }

    for (int kt = 0; kt < NK; kt++) {
        asm volatile("cp.async.wait_group %0;" :: "n"(NSTAGE - 2) : "memory");
        __syncthreads();

        // issue next stage (slot (kt+3)&3 was fully consumed in iter kt-1)
        if (kt + NSTAGE - 1 < NK) load_stage(kt + NSTAGE - 1, (kt + NSTAGE - 1) & (NSTAGE - 1));
        CP_COMMIT();

        const uint32_t st = sb + (kt & (NSTAGE - 1)) * STAGE_BYTES;
        const uint32_t aB = st + aoff;
        const uint32_t bB = st + boff;

        uint32_t ah[2][4], al[2][4];
        ldsm_x4(ah[0], aB);
        ldsm_x4(ah[1], aB + 16 * RS_);
        ldsm_x4(al[0], aB + ARR_BYTES);
        ldsm_x4(al[1], aB + ARR_BYTES + 16 * RS_);
        #pragma unroll
        for (int np = 0; np < 4; np++) {
            uint32_t bh[4], bl[4];
            ldsm_x4(bh, bB + np * 16 * RS_);
            ldsm_x4(bl, bB + ARR_BYTES + np * 16 * RS_);
            #pragma unroll
            for (int s = 0; s < 2; s++) {
                const int nt = 2 * np + s;
                #pragma unroll
                for (int mt = 0; mt < 2; mt++) {
                    mma_bf16(acc[mt][nt], ah[mt][0], ah[mt][1], ah[mt][2], ah[mt][3], bh[2*s], bh[2*s+1]);
                    mma_bf16(acc[mt][nt], ah[mt][0], ah[mt][1], ah[mt][2], ah[mt][3], bl[2*s], bl[2*s+1]);
                    mma_bf16(acc[mt][nt], al[mt][0], al[mt][1], al[mt][2], al[mt][3], bh[2*s], bh[2*s+1]);
                }
            }
        }
    }

    // ---- epilogue: + bias, head-major scatter ----
    const int lr = lane >> 2;
    const int lc = (lane & 3) * 2;
    #pragma unroll
    for (int nt = 0; nt < 8; nt++) {
        int n0 = bn + wn + (nt >> 1) * 16 + (nt & 1) * 8 + lc;
        int h = n0 >> 6, d0 = n0 & 63;
        float2 b2 = *(const float2*)(bias + n0);
        #pragma unroll
        for (int mt = 0; mt < 2; mt++) {
            int m0 = bm + wm + mt * 16 + lr;
            #pragma unroll
            for (int half = 0; half < 2; half++) {
                int m = m0 + half * 8;
                size_t dst;
                if (MODE == 0) {
                    int b = m >> 12, ls = m & (T_ - 1);
                    dst = ((size_t)(b * H_ + h) * T_ + ls) * DH_ + d0;
                } else {
                    dst = ((size_t)(batch * H_ + h) * TP_ + m) * DH_ + d0;
                }
                float2 o;
                o.x = acc[mt][nt][2 * half + 0] + b2.x;
                o.y = acc[mt][nt][2 * half + 1] + b2.y;
                *(float2*)(outp + dst) = o;
            }
        }
    }
}

// ---------------- 5) attention over compacted keys (fp32 SIMT) --------------
__global__ void __launch_bounds__(256)
attn_kernel(float* __restrict__ out)
{
    __shared__ float Qs[64][68];
    __shared__ float Kst[64][34];
    __shared__ float Vs[32][68];
    __shared__ float Ps[64][33];

    const int b = blockIdx.z, h = blockIdx.y, q0 = blockIdx.x * 64;
    const int tid = threadIdx.x;
    const int tx = tid & 15, ty = tid >> 4;
    const int cnt = g_cnt[b];
    const int ntiles = (cnt + 31) >> 5;

    const float* Qg = g_Q + ((size_t)(b * H_ + h) * T_ + q0) * DH_;
    const float* Kg = g_K + ((size_t)(b * H_ + h) * TP_) * DH_;
    const float* Vg = g_V + ((size_t)(b * H_ + h) * TP_) * DH_;

    for (int idx = tid; idx < 64 * 16; idx += 256) {
        int r = idx >> 4, c4 = (idx & 15) * 4;
        float4 v = *(const float4*)(Qg + (size_t)r * DH_ + c4);
        v.x *= 0.125f; v.y *= 0.125f; v.z *= 0.125f; v.w *= 0.125f;
        *(float4*)&Qs[r][c4] = v;
    }

    float acc[4][4];
    #pragma unroll
    for (int i = 0; i < 4; i++)
        #pragma unroll
        for (int j = 0; j < 4; j++) acc[i][j] = 0.0f;
    float mrow[4], lrow[4];
    #pragma unroll
    for (int i = 0; i < 4; i++) { mrow[i] = -1e30f; lrow[i] = 0.0f; }

    for (int t = 0; t < ntiles; t++) {
        const int kb = t * 32;
        __syncthreads();
        for (int idx = tid; idx < 512; idx += 256) {
            int c4 = idx >> 5, key = idx & 31;
            float4 v = *(const float4*)(Kg + (size_t)(kb + key) * DH_ + c4 * 4);
            Kst[c4 * 4 + 0][key] = v.x;
            Kst[c4 * 4 + 1][key] = v.y;
            Kst[c4 * 4 + 2][key] = v.z;
            Kst[c4 * 4 + 3][key] = v.w;
        }
        for (int idx = tid; idx < 512; idx += 256) {
            int r = idx >> 4, c4 = (idx & 15) * 4;
            *(float4*)&Vs[r][c4] = *(const float4*)(Vg + (size_t)(kb + r) * DH_ + c4);
        }
        __syncthreads();

        float s[4][2];
        #pragma unroll
        for (int i = 0; i < 4; i++) { s[i][0] = 0.0f; s[i][1] = 0.0f; }
        #pragma unroll
        for (int d = 0; d < 64; d++) {
            float2 bk2 = *(const float2*)&Kst[d][2 * tx];
            #pragma unroll
            for (int i = 0; i < 4; i++) {
                float a = Qs[4 * ty + i][d];
                s[i][0] = fmaf(a, bk2.x, s[i][0]);
                s[i][1] = fmaf(a, bk2.y, s[i][1]);
            }
        }
        #pragma unroll
        for (int j = 0; j < 2; j++)
            if (kb + 2 * tx + j >= cnt) {
                #pragma unroll
                for (int i = 0; i < 4; i++) s[i][j] = -1e30f;
            }

        #pragma unroll
        for (int i = 0; i < 4; i++) {
            float tm = fmaxf(s[i][0], s[i][1]);
            #pragma unroll
            for (int off = 8; off >= 1; off >>= 1)
                tm = fmaxf(tm, __shfl_xor_sync(0xffffffffu, tm, off));
            float mn = fmaxf(mrow[i], tm);
            float p0 = __expf(s[i][0] - mn);
            float p1 = __expf(s[i][1] - mn);
            Ps[4 * ty + i][2 * tx]     = p0;
            Ps[4 * ty + i][2 * tx + 1] = p1;
            float ts = p0 + p1;
            #pragma unroll
            for (int off = 8; off >= 1; off >>= 1)
                ts += __shfl_xor_sync(0xffffffffu, ts, off);
            float alpha = __expf(mrow[i] - mn);
            lrow[i] = lrow[i] * alpha + ts;
            mrow[i] = mn;
            #pragma unroll
            for (int j = 0; j < 4; j++) acc[i][j] *= alpha;
        }
        __syncwarp();

        #pragma unroll
        for (int kk = 0; kk < 32; kk++) {
            float v4[4];
            *(float4*)v4 = *(const float4*)&Vs[kk][4 * tx];
            #pragma unroll
            for (int i = 0; i < 4; i++) {
                float p = Ps[4 * ty + i][kk];
                #pragma unroll
                for (int j = 0; j < 4; j++)
                    acc[i][j] = fmaf(p, v4[j], acc[i][j]);
            }
        }
    }

    #pragma unroll
    for (int i = 0; i < 4; i++) {
        int row = 4 * ty + i;
        float inv = 1.0f / lrow[i];
        float4 r;
        r.x = acc[i][0] * inv; r.y = acc[i][1] * inv;
        r.z = acc[i][2] * inv; r.w = acc[i][3] * inv;
        *(float4*)(out + ((size_t)(b * T_ + q0 + row)) * D_ + h * DH_ + 4 * tx) = r;
    }
}

// ---------------- launch -----------------------------------------------------
extern "C" void kernel_launch(void* const* d_in, const int* in_sizes, int n_in,
                              void* d_out, int out_size) {
    const float* hs = (const float*)d_in[0];
    const int*   am = (const int*)d_in[1];
    const float* Wq = (const float*)d_in[2];
    const float* bq = (const float*)d_in[3];
    const float* Wk = (const float*)d_in[4];
    const float* bk = (const float*)d_in[5];
    const float* Wv = (const float*)d_in[6];
    const float* bv = (const float*)d_in[7];
    float* out = (float*)d_out;

    cudaFuncSetAttribute(gemm_mma_kernel<0>, cudaFuncAttributeMaxDynamicSharedMemorySize, SMEM_GEMM);
    cudaFuncSetAttribute(gemm_mma_kernel<1>, cudaFuncAttributeMaxDynamicSharedMemorySize, SMEM_GEMM);

    wsplit_kernel<<<3 * W4_ / 256, 256>>>(Wq, Wk, Wv);
    hs_pool_split_kernel<<<(B_ * TP_ * D_ / 4) / 256, 256>>>(hs);
    mask_kernel<<<B_, TP_>>>(am);
    gemm_mma_kernel<0><<<dim3(D_ / 128, (B_ * T_) / 128, 1), 256, SMEM_GEMM>>>(bq, nullptr, nullptr);
    gemm_mma_kernel<1><<<dim3(D_ / 128, TP_ / 128, 2 * B_), 256, SMEM_GEMM>>>(nullptr, bk, bv);
    attn_kernel<<<dim3(T_ / 64, H_, B_), 256>>>(out);
}

// round 8
// speedup vs baseline: 2.5865x; 1.2649x over previous
#include <cuda_runtime.h>
#include <cuda_fp16.h>
#include <cstdint>

#define B_  2
#define T_  4096
#define D_  1024
#define H_  16
#define DH_ 64
#define KP_ 4
#define TP_ 1024
#define NSPLIT 4

// ---------------- scratch (device globals; no allocations allowed) ----------
__device__ __half g_hs_hi[(size_t)B_ * T_ * D_];
__device__ __half g_hs_lo[(size_t)B_ * T_ * D_];
__device__ __half g_phi[B_ * TP_ * D_];
__device__ __half g_plo[B_ * TP_ * D_];
__device__ __half g_Wq[D_ * D_], g_Wk[D_ * D_], g_Wv[D_ * D_];
__device__ float g_Q[(size_t)B_ * H_ * T_ * DH_];   // [B,H,T,DH]
__device__ float g_K[(size_t)B_ * H_ * TP_ * DH_];  // [B,H,TP,DH] compacted
__device__ float g_V[(size_t)B_ * H_ * TP_ * DH_];
// split-K partials: [split][sel][batch][H][TP][DH]
__device__ float g_KVp[(size_t)NSPLIT * 2 * B_ * H_ * TP_ * DH_];
__device__ int   g_act[B_ * TP_];
__device__ int   g_cnt[B_];

// ---------------- helpers ----------------------------------------------------
__device__ __forceinline__ uint32_t smem_u32(const void* p) {
    uint32_t a;
    asm("{ .reg .u64 t; cvta.to.shared.u64 t, %1; cvt.u32.u64 %0, t; }" : "=r"(a) : "l"(p));
    return a;
}
#define CP_ASYNC16(dst, src) \
    asm volatile("cp.async.cg.shared.global [%0], [%1], 16;" :: "r"(dst), "l"(src))
#define CP_COMMIT() asm volatile("cp.async.commit_group;" ::: "memory")

__device__ __forceinline__ void mma_f16(float* c,
        uint32_t a0, uint32_t a1, uint32_t a2, uint32_t a3,
        uint32_t b0, uint32_t b1) {
    asm volatile("mma.sync.aligned.m16n8k16.row.col.f32.f16.f16.f32 "
        "{%0,%1,%2,%3}, {%4,%5,%6,%7}, {%8,%9}, {%0,%1,%2,%3};"
        : "+f"(c[0]), "+f"(c[1]), "+f"(c[2]), "+f"(c[3])
        : "r"(a0), "r"(a1), "r"(a2), "r"(a3), "r"(b0), "r"(b1));
}
__device__ __forceinline__ void ldsm_x4(uint32_t* r, uint32_t addr) {
    asm volatile("ldmatrix.sync.aligned.m8n8.x4.shared.b16 {%0,%1,%2,%3}, [%4];"
        : "=r"(r[0]), "=r"(r[1]), "=r"(r[2]), "=r"(r[3]) : "r"(addr));
}
__device__ __forceinline__ void split1h(float v, unsigned short& h, unsigned short& l) {
    __half hh = __float2half_rn(v);
    float f = v - __half2float(hh);
    h = __half_as_ushort(hh);
    l = __half_as_ushort(__float2half_rn(f));
}

// ---------------- 1) weight fp16 conversion (Wq, Wk, Wv, one launch) ---------
#define W4_ (D_ * D_ / 4)
__global__ void wconv_kernel(const float* __restrict__ Wq,
                             const float* __restrict__ Wk,
                             const float* __restrict__ Wv) {
    int p = blockIdx.x * blockDim.x + threadIdx.x;
    const float* src;
    __half* dst;
    int seg = p / W4_, off = p - seg * W4_;
    if (seg == 0)      { src = Wq; dst = g_Wq; }
    else if (seg == 1) { src = Wk; dst = g_Wk; }
    else               { src = Wv; dst = g_Wv; }
    float4 v = ((const float4*)src)[off];
    ushort4 h;
    h.x = __half_as_ushort(__float2half_rn(v.x));
    h.y = __half_as_ushort(__float2half_rn(v.y));
    h.z = __half_as_ushort(__float2half_rn(v.z));
    h.w = __half_as_ushort(__float2half_rn(v.w));
    ((ushort4*)dst)[off] = h;
}

// ---------------- 2) hs split + avgpool + pooled split (single hs pass) -----
__global__ void hs_pool_split_kernel(const float* __restrict__ hs) {
    int p = blockIdx.x * blockDim.x + threadIdx.x;
    int d4  = p & 255;
    int row = p >> 8;
    const float4* src = (const float4*)hs;
    size_t base = (size_t)row * (KP_ * 256) + d4;
    float4 s[4];
    #pragma unroll
    for (int r = 0; r < 4; r++) s[r] = src[base + r * 256];
    #pragma unroll
    for (int r = 0; r < 4; r++) {
        ushort4 h, l;
        split1h(s[r].x, h.x, l.x); split1h(s[r].y, h.y, l.y);
        split1h(s[r].z, h.z, l.z); split1h(s[r].w, h.w, l.w);
        ((ushort4*)g_hs_hi)[base + r * 256] = h;
        ((ushort4*)g_hs_lo)[base + r * 256] = l;
    }
    float m[4];
    m[0] = (s[0].x + s[1].x + s[2].x + s[3].x) * 0.25f;
    m[1] = (s[0].y + s[1].y + s[2].y + s[3].y) * 0.25f;
    m[2] = (s[0].z + s[1].z + s[2].z + s[3].z) * 0.25f;
    m[3] = (s[0].w + s[1].w + s[2].w + s[3].w) * 0.25f;
    ushort4 h, l;
    split1h(m[0], h.x, l.x); split1h(m[1], h.y, l.y);
    split1h(m[2], h.z, l.z); split1h(m[3], h.w, l.w);
    ((ushort4*)g_phi)[p] = h;
    ((ushort4*)g_plo)[p] = l;
}

// ---------------- 3) mask -> compacted active-key list ----------------------
__global__ void mask_kernel(const int* __restrict__ am) {
    __shared__ int sc[TP_];
    int b = blockIdx.x, tt = threadIdx.x;
    const int* m = am + b * T_ + tt * KP_;
    int s = m[0] + m[1] + m[2] + m[3];
    int act = (s == 0) ? 1 : 0;
    sc[tt] = act;
    __syncthreads();
    for (int off = 1; off < TP_; off <<= 1) {
        int v = 0;
        if (tt >= off) v = sc[tt - off];
        __syncthreads();
        sc[tt] += v;
        __syncthreads();
    }
    int total = sc[TP_ - 1];
    if (total == 0) {
        g_act[b * TP_ + tt] = tt;
        if (tt == 0) g_cnt[b] = TP_;
    } else {
        if (act) g_act[b * TP_ + sc[tt] - 1] = tt;
        if (tt >= total) g_act[b * TP_ + tt] = 0;
        if (tt == 0) g_cnt[b] = total;
    }
}

// ---------------- 4) mma.sync fp16x2 projection GEMM ------------------------
// C = (Ah + Al) @ W^T, A split in fp16 (A exact to ~2^-23), W single fp16.
// 128x128 CTA tile, 8 warps (warp 32x64), ldmatrix fragments.
// 4-stage cp.async pipeline, one k16 per stage, one __syncthreads per iter.
// Row stride 48B: 16B-aligned (ldmatrix requires) + conflict-free phases.
// MODE 0: Q (A = hs).  MODE 1: split-K KV (A = pooled gathered; raw partials).
#define RS_ 48
#define ARR_BYTES (128 * RS_)        // 6144
#define STAGE_BYTES (3 * ARR_BYTES)  // 18432 (Ah, Al, W)
#define NSTAGE 4
#define SMEM_GEMM (NSTAGE * STAGE_BYTES)  // 73728

template<int MODE>
__global__ void __launch_bounds__(256, 2)
gemm_mma_kernel(const float* __restrict__ bq_)
{
    extern __shared__ char smc[];
    const uint32_t sb = smem_u32(smc);
    const int tid = threadIdx.x;
    const int wid = tid >> 5, lane = tid & 31;
    const int bn = blockIdx.x * 128;
    const int bm = blockIdx.y * 128;

    const __half *Ah, *Al, *W;
    float* outp;
    int batch = 0, kbase = 0, NK;
    if (MODE == 0) {
        Ah = g_hs_hi; Al = g_hs_lo; W = g_Wq;
        outp = g_Q;
        NK = D_ / 16;
    } else {
        int z = blockIdx.z;
        batch = z & 1;
        int sel = (z >> 1) & 1;
        int split = z >> 2;
        if (bm >= g_cnt[batch]) return;
        Ah = g_phi; Al = g_plo;
        W = sel ? g_Wv : g_Wk;
        outp = g_KVp + ((size_t)(split * 2 + sel) * B_ + batch) * ((size_t)H_ * TP_ * DH_);
        kbase = split * (D_ / NSPLIT);   // 256 elements per split
        NK = (D_ / NSPLIT) / 16;         // 16
    }

    // per-thread load assignment: 768 cp.async16 per stage, 3 per thread
    const __half* srcb[3];
    {
        int r0 = (tid >> 1) & 127;
        size_t arow;
        if (MODE == 0) arow = (size_t)(bm + r0);
        else arow = (size_t)batch * TP_ + g_act[batch * TP_ + bm + r0];
        size_t wrow = (size_t)(bn + r0);
        srcb[0] = Ah + arow * D_;
        srcb[1] = Al + arow * D_;
        srcb[2] = W + wrow * D_;
    }
    const int lc16 = (tid & 1) * 8;

    auto load_stage = [&](int kt, int stage) {
        const uint32_t dbase = sb + stage * STAGE_BYTES
                             + (((tid >> 1) & 127) * RS_) + (tid & 1) * 16;
        const int koff = kbase + kt * 16 + lc16;
        #pragma unroll
        for (int a = 0; a < 3; a++)
            CP_ASYNC16(dbase + a * ARR_BYTES, srcb[a] + koff);
    };

    float acc[2][8][4];
    #pragma unroll
    for (int mt = 0; mt < 2; mt++)
        #pragma unroll
        for (int nt = 0; nt < 8; nt++)
            #pragma unroll
            for (int j = 0; j < 4; j++) acc[mt][nt][j] = 0.0f;

    const int wm = (wid & 3) * 32;
    const int wn = (wid >> 2) * 64;

    const int arow = (lane & 7) + ((lane >> 3) & 1) * 8;
    const int akh  = lane >> 4;
    const int brow = (lane & 7) + (lane >> 4) * 8;
    const int bkh  = (lane >> 3) & 1;
    const uint32_t aoff = (uint32_t)((wm + arow) * RS_ + akh * 16);
    const uint32_t boff = (uint32_t)(2 * ARR_BYTES + (wn + brow) * RS_ + bkh * 16);

    // prologue: 3 stages in flight
    #pragma unroll
    for (int s = 0; s < NSTAGE - 1; s++) { load_stage(s, s); CP_COMMIT(); }

    for (int kt = 0; kt < NK; kt++) {
        asm volatile("cp.async.wait_group %0;" :: "n"(NSTAGE - 2) : "memory");
        __syncthreads();

        if (kt + NSTAGE - 1 < NK) load_stage(kt + NSTAGE - 1, (kt + NSTAGE - 1) & (NSTAGE - 1));
        CP_COMMIT();

        const uint32_t st = sb + (kt & (NSTAGE - 1)) * STAGE_BYTES;
        const uint32_t aB = st + aoff;
        const uint32_t bB = st + boff;

        uint32_t ah[2][4], al[2][4];
        ldsm_x4(ah[0], aB);
        ldsm_x4(ah[1], aB + 16 * RS_);
        ldsm_x4(al[0], aB + ARR_BYTES);
        ldsm_x4(al[1], aB + ARR_BYTES + 16 * RS_);
        #pragma unroll
        for (int np = 0; np < 4; np++) {
            uint32_t bw[4];
            ldsm_x4(bw, bB + np * 16 * RS_);
            #pragma unroll
            for (int s = 0; s < 2; s++) {
                const int nt = 2 * np + s;
                #pragma unroll
                for (int mt = 0; mt < 2; mt++) {
                    mma_f16(acc[mt][nt], ah[mt][0], ah[mt][1], ah[mt][2], ah[mt][3], bw[2*s], bw[2*s+1]);
                    mma_f16(acc[mt][nt], al[mt][0], al[mt][1], al[mt][2], al[mt][3], bw[2*s], bw[2*s+1]);
                }
            }
        }
    }

    // ---- epilogue ----
    const int lr = lane >> 2;
    const int lc = (lane & 3) * 2;
    #pragma unroll
    for (int nt = 0; nt < 8; nt++) {
        int c0 = bn + wn + (nt >> 1) * 16 + (nt & 1) * 8 + lc;
        int h = c0 >> 6, d0 = c0 & 63;
        float2 b2 = make_float2(0.0f, 0.0f);
        if (MODE == 0) b2 = *(const float2*)(bq_ + c0);
        #pragma unroll
        for (int mt = 0; mt < 2; mt++) {
            int m0 = bm + wm + mt * 16 + lr;
            #pragma unroll
            for (int half = 0; half < 2; half++) {
                int m = m0 + half * 8;
                size_t dst;
                if (MODE == 0) {
                    int b = m >> 12, ls = m & (T_ - 1);
                    dst = ((size_t)(b * H_ + h) * T_ + ls) * DH_ + d0;
                } else {
                    dst = ((size_t)h * TP_ + m) * DH_ + d0;
                }
                float2 o;
                o.x = acc[mt][nt][2 * half + 0] + b2.x;
                o.y = acc[mt][nt][2 * half + 1] + b2.y;
                *(float2*)(outp + dst) = o;
            }
        }
    }
}

// ---------------- 5) split-K reduce + bias for K/V ---------------------------
__global__ void kv_reduce_kernel(const float* __restrict__ bk,
                                 const float* __restrict__ bv) {
    int p = blockIdx.x * blockDim.x + threadIdx.x;  // float4 index
    int d4  = p & 15;
    int i   = (p >> 4) & (TP_ - 1);
    int h   = (p >> 14) & (H_ - 1);
    int b   = (p >> 18) & (B_ - 1);
    int sel = (p >> 19) & 1;
    if (i >= g_cnt[b]) return;
    float4 acc = make_float4(0.f, 0.f, 0.f, 0.f);
    #pragma unroll
    for (int sp = 0; sp < NSPLIT; sp++) {
        const float* base = g_KVp
            + ((size_t)(sp * 2 + sel) * B_ + b) * ((size_t)H_ * TP_ * DH_)
            + ((size_t)h * TP_ + i) * DH_;
        float4 v = ((const float4*)base)[d4];
        acc.x += v.x; acc.y += v.y; acc.z += v.z; acc.w += v.w;
    }
    const float* bias = sel ? bv : bk;
    float4 bb = ((const float4*)(bias + h * DH_))[d4];
    acc.x += bb.x; acc.y += bb.y; acc.z += bb.z; acc.w += bb.w;
    float* outp = sel ? g_V : g_K;
    ((float4*)(outp + ((size_t)(b * H_ + h) * TP_ + i) * DH_))[d4] = acc;
}

// ---------------- 6) attention over compacted keys (fp32 SIMT) --------------
__global__ void __launch_bounds__(256)
attn_kernel(float* __restrict__ out)
{
    __shared__ float Qs[64][68];
    __shared__ float Kst[64][34];
    __shared__ float Vs[32][68];
    __shared__ float Ps[64][33];

    const int b = blockIdx.z, h = blockIdx.y, q0 = blockIdx.x * 64;
    const int tid = threadIdx.x;
    const int tx = tid & 15, ty = tid >> 4;
    const int cnt = g_cnt[b];
    const int ntiles = (cnt + 31) >> 5;

    const float* Qg = g_Q + ((size_t)(b * H_ + h) * T_ + q0) * DH_;
    const float* Kg = g_K + ((size_t)(b * H_ + h) * TP_) * DH_;
    const float* Vg = g_V + ((size_t)(b * H_ + h) * TP_) * DH_;

    for (int idx = tid; idx < 64 * 16; idx += 256) {
        int r = idx >> 4, c4 = (idx & 15) * 4;
        float4 v = *(const float4*)(Qg + (size_t)r * DH_ + c4);
        v.x *= 0.125f; v.y *= 0.125f; v.z *= 0.125f; v.w *= 0.125f;
        *(float4*)&Qs[r][c4] = v;
    }

    float acc[4][4];
    #pragma unroll
    for (int i = 0; i < 4; i++)
        #pragma unroll
        for (int j = 0; j < 4; j++) acc[i][j] = 0.0f;
    float mrow[4], lrow[4];
    #pragma unroll
    for (int i = 0; i < 4; i++) { mrow[i] = -1e30f; lrow[i] = 0.0f; }

    for (int t = 0; t < ntiles; t++) {
        const int kb = t * 32;
        __syncthreads();
        for (int idx = tid; idx < 512; idx += 256) {
            int c4 = idx >> 5, key = idx & 31;
            float4 v = *(const float4*)(Kg + (size_t)(kb + key) * DH_ + c4 * 4);
            Kst[c4 * 4 + 0][key] = v.x;
            Kst[c4 * 4 + 1][key] = v.y;
            Kst[c4 * 4 + 2][key] = v.z;
            Kst[c4 * 4 + 3][key] = v.w;
        }
        for (int idx = tid; idx < 512; idx += 256) {
            int r = idx >> 4, c4 = (idx & 15) * 4;
            *(float4*)&Vs[r][c4] = *(const float4*)(Vg + (size_t)(kb + r) * DH_ + c4);
        }
        __syncthreads();

        float s[4][2];
        #pragma unroll
        for (int i = 0; i < 4; i++) { s[i][0] = 0.0f; s[i][1] = 0.0f; }
        #pragma unroll
        for (int d = 0; d < 64; d++) {
            float2 bk2 = *(const float2*)&Kst[d][2 * tx];
            #pragma unroll
            for (int i = 0; i < 4; i++) {
                float a = Qs[4 * ty + i][d];
                s[i][0] = fmaf(a, bk2.x, s[i][0]);
                s[i][1] = fmaf(a, bk2.y, s[i][1]);
            }
        }
        #pragma unroll
        for (int j = 0; j < 2; j++)
            if (kb + 2 * tx + j >= cnt) {
                #pragma unroll
                for (int i = 0; i < 4; i++) s[i][j] = -1e30f;
            }

        #pragma unroll
        for (int i = 0; i < 4; i++) {
            float tm = fmaxf(s[i][0], s[i][1]);
            #pragma unroll
            for (int off = 8; off >= 1; off >>= 1)
                tm = fmaxf(tm, __shfl_xor_sync(0xffffffffu, tm, off));
            float mn = fmaxf(mrow[i], tm);
            float p0 = __expf(s[i][0] - mn);
            float p1 = __expf(s[i][1] - mn);
            Ps[4 * ty + i][2 * tx]     = p0;
            Ps[4 * ty + i][2 * tx + 1] = p1;
            float ts = p0 + p1;
            #pragma unroll
            for (int off = 8; off >= 1; off >>= 1)
                ts += __shfl_xor_sync(0xffffffffu, ts, off);
            float alpha = __expf(mrow[i] - mn);
            lrow[i] = lrow[i] * alpha + ts;
            mrow[i] = mn;
            #pragma unroll
            for (int j = 0; j < 4; j++) acc[i][j] *= alpha;
        }
        __syncwarp();

        #pragma unroll
        for (int kk = 0; kk < 32; kk++) {
            float v4[4];
            *(float4*)v4 = *(const float4*)&Vs[kk][4 * tx];
            #pragma unroll
            for (int i = 0; i < 4; i++) {
                float p = Ps[4 * ty + i][kk];
                #pragma unroll
                for (int j = 0; j < 4; j++)
                    acc[i][j] = fmaf(p, v4[j], acc[i][j]);
            }
        }
    }

    #pragma unroll
    for (int i = 0; i < 4; i++) {
        int row = 4 * ty + i;
        float inv = 1.0f / lrow[i];
        float4 r;
        r.x = acc[i][0] * inv; r.y = acc[i][1] * inv;
        r.z = acc[i][2] * inv; r.w = acc[i][3] * inv;
        *(float4*)(out + ((size_t)(b * T_ + q0 + row)) * D_ + h * DH_ + 4 * tx) = r;
    }
}

// ---------------- launch -----------------------------------------------------
extern "C" void kernel_launch(void* const* d_in, const int* in_sizes, int n_in,
                              void* d_out, int out_size) {
    const float* hs = (const float*)d_in[0];
    const int*   am = (const int*)d_in[1];
    const float* Wq = (const float*)d_in[2];
    const float* bq = (const float*)d_in[3];
    const float* Wk = (const float*)d_in[4];
    const float* bk = (const float*)d_in[5];
    const float* Wv = (const float*)d_in[6];
    const float* bv = (const float*)d_in[7];
    float* out = (float*)d_out;

    cudaFuncSetAttribute(gemm_mma_kernel<0>, cudaFuncAttributeMaxDynamicSharedMemorySize, SMEM_GEMM);
    cudaFuncSetAttribute(gemm_mma_kernel<1>, cudaFuncAttributeMaxDynamicSharedMemorySize, SMEM_GEMM);

    wconv_kernel<<<3 * W4_ / 256, 256>>>(Wq, Wk, Wv);
    hs_pool_split_kernel<<<(B_ * TP_ * D_ / 4) / 256, 256>>>(hs);
    mask_kernel<<<B_, TP_>>>(am);
    gemm_mma_kernel<0><<<dim3(D_ / 128, (B_ * T_) / 128, 1), 256, SMEM_GEMM>>>(bq);
    gemm_mma_kernel<1><<<dim3(D_ / 128, TP_ / 128, 4 * NSPLIT), 256, SMEM_GEMM>>>(nullptr);
    kv_reduce_kernel<<<(2 * B_ * H_ * TP_ * (DH_ / 4)) / 256, 256>>>(bk, bv);
    attn_kernel<<<dim3(T_ / 64, H_, B_), 256>>>(out);
}

// round 9
// speedup vs baseline: 3.2453x; 1.2547x over previous
#include <cuda_runtime.h>
#include <cuda_fp16.h>
#include <cstdint>

#define B_  2
#define T_  4096
#define D_  1024
#define H_  16
#define DH_ 64
#define KP_ 4
#define TP_ 1024
#define NSPLIT 4

// ---------------- scratch (device globals; no allocations allowed) ----------
__device__ __half g_hs[(size_t)B_ * T_ * D_];
__device__ __half g_pool[B_ * TP_ * D_];
__device__ __half g_Wq[D_ * D_], g_Wk[D_ * D_], g_Wv[D_ * D_];
__device__ float g_Q[(size_t)B_ * H_ * T_ * DH_];   // [B,H,T,DH]
__device__ float g_K[(size_t)B_ * H_ * TP_ * DH_];  // [B,H,TP,DH] compacted
__device__ float g_V[(size_t)B_ * H_ * TP_ * DH_];
// split-K partials: [split][sel][batch][H][TP][DH]
__device__ float g_KVp[(size_t)NSPLIT * 2 * B_ * H_ * TP_ * DH_];
__device__ int   g_act[B_ * TP_];
__device__ int   g_cnt[B_];

// ---------------- helpers ----------------------------------------------------
__device__ __forceinline__ uint32_t smem_u32(const void* p) {
    uint32_t a;
    asm("{ .reg .u64 t; cvta.to.shared.u64 t, %1; cvt.u32.u64 %0, t; }" : "=r"(a) : "l"(p));
    return a;
}
#define CP_ASYNC16(dst, src) \
    asm volatile("cp.async.cg.shared.global [%0], [%1], 16;" :: "r"(dst), "l"(src))
#define CP_COMMIT() asm volatile("cp.async.commit_group;" ::: "memory")

__device__ __forceinline__ void mma_f16(float* c,
        uint32_t a0, uint32_t a1, uint32_t a2, uint32_t a3,
        uint32_t b0, uint32_t b1) {
    asm volatile("mma.sync.aligned.m16n8k16.row.col.f32.f16.f16.f32 "
        "{%0,%1,%2,%3}, {%4,%5,%6,%7}, {%8,%9}, {%0,%1,%2,%3};"
        : "+f"(c[0]), "+f"(c[1]), "+f"(c[2]), "+f"(c[3])
        : "r"(a0), "r"(a1), "r"(a2), "r"(a3), "r"(b0), "r"(b1));
}
__device__ __forceinline__ void ldsm_x4(uint32_t* r, uint32_t addr) {
    asm volatile("ldmatrix.sync.aligned.m8n8.x4.shared.b16 {%0,%1,%2,%3}, [%4];"
        : "=r"(r[0]), "=r"(r[1]), "=r"(r[2]), "=r"(r[3]) : "r"(addr));
}

// ---------------- 1) weight fp16 conversion (Wq, Wk, Wv, one launch) ---------
#define W4_ (D_ * D_ / 4)
__global__ void wconv_kernel(const float* __restrict__ Wq,
                             const float* __restrict__ Wk,
                             const float* __restrict__ Wv) {
    int p = blockIdx.x * blockDim.x + threadIdx.x;
    const float* src;
    __half* dst;
    int seg = p / W4_, off = p - seg * W4_;
    if (seg == 0)      { src = Wq; dst = g_Wq; }
    else if (seg == 1) { src = Wk; dst = g_Wk; }
    else               { src = Wv; dst = g_Wv; }
    float4 v = ((const float4*)src)[off];
    ushort4 h;
    h.x = __half_as_ushort(__float2half_rn(v.x));
    h.y = __half_as_ushort(__float2half_rn(v.y));
    h.z = __half_as_ushort(__float2half_rn(v.z));
    h.w = __half_as_ushort(__float2half_rn(v.w));
    ((ushort4*)dst)[off] = h;
}

// ---------------- 2) hs fp16 + avgpool fp16 (single hs pass) -----------------
__global__ void hs_pool_kernel(const float* __restrict__ hs) {
    int p = blockIdx.x * blockDim.x + threadIdx.x;
    int d4  = p & 255;
    int row = p >> 8;
    const float4* src = (const float4*)hs;
    size_t base = (size_t)row * (KP_ * 256) + d4;
    float4 s[4];
    #pragma unroll
    for (int r = 0; r < 4; r++) s[r] = src[base + r * 256];
    #pragma unroll
    for (int r = 0; r < 4; r++) {
        ushort4 h;
        h.x = __half_as_ushort(__float2half_rn(s[r].x));
        h.y = __half_as_ushort(__float2half_rn(s[r].y));
        h.z = __half_as_ushort(__float2half_rn(s[r].z));
        h.w = __half_as_ushort(__float2half_rn(s[r].w));
        ((ushort4*)g_hs)[base + r * 256] = h;
    }
    ushort4 h;
    h.x = __half_as_ushort(__float2half_rn((s[0].x + s[1].x + s[2].x + s[3].x) * 0.25f));
    h.y = __half_as_ushort(__float2half_rn((s[0].y + s[1].y + s[2].y + s[3].y) * 0.25f));
    h.z = __half_as_ushort(__float2half_rn((s[0].z + s[1].z + s[2].z + s[3].z) * 0.25f));
    h.w = __half_as_ushort(__float2half_rn((s[0].w + s[1].w + s[2].w + s[3].w) * 0.25f));
    ((ushort4*)g_pool)[p] = h;
}

// ---------------- 3) mask -> compacted active-key list ----------------------
__global__ void mask_kernel(const int* __restrict__ am) {
    __shared__ int sc[TP_];
    int b = blockIdx.x, tt = threadIdx.x;
    const int* m = am + b * T_ + tt * KP_;
    int s = m[0] + m[1] + m[2] + m[3];
    int act = (s == 0) ? 1 : 0;
    sc[tt] = act;
    __syncthreads();
    for (int off = 1; off < TP_; off <<= 1) {
        int v = 0;
        if (tt >= off) v = sc[tt - off];
        __syncthreads();
        sc[tt] += v;
        __syncthreads();
    }
    int total = sc[TP_ - 1];
    if (total == 0) {
        g_act[b * TP_ + tt] = tt;
        if (tt == 0) g_cnt[b] = TP_;
    } else {
        if (act) g_act[b * TP_ + sc[tt] - 1] = tt;
        if (tt >= total) g_act[b * TP_ + tt] = 0;
        if (tt == 0) g_cnt[b] = total;
    }
}

// ---------------- 4) mma.sync fp16 projection GEMM ---------------------------
// C = A @ W^T (both fp16, fp32 accum). 128x128 CTA tile, 8 warps (32x64).
// 4-stage cp.async pipeline, one k16 per stage, one __syncthreads per iter.
// Row stride 48B: 16B-aligned (ldmatrix) + conflict-free 8-row phases.
// MODE 0: Q (A = hs, +bias).  MODE 1: split-K KV (A = pooled gathered).
#define RS_ 48
#define ARR_BYTES (128 * RS_)        // 6144
#define STAGE_BYTES (2 * ARR_BYTES)  // 12288 (A, W)
#define NSTAGE 4
#define SMEM_GEMM (NSTAGE * STAGE_BYTES)  // 49152

template<int MODE>
__global__ void __launch_bounds__(256, 2)
gemm_mma_kernel(const float* __restrict__ bq_)
{
    extern __shared__ char smc[];
    const uint32_t sb = smem_u32(smc);
    const int tid = threadIdx.x;
    const int wid = tid >> 5, lane = tid & 31;
    const int bn = blockIdx.x * 128;
    const int bm = blockIdx.y * 128;

    const __half *A, *W;
    float* outp;
    int batch = 0, kbase = 0, NK;
    if (MODE == 0) {
        A = g_hs; W = g_Wq;
        outp = g_Q;
        NK = D_ / 16;
    } else {
        int z = blockIdx.z;
        batch = z & 1;
        int sel = (z >> 1) & 1;
        int split = z >> 2;
        if (bm >= g_cnt[batch]) return;
        A = g_pool;
        W = sel ? g_Wv : g_Wk;
        outp = g_KVp + ((size_t)(split * 2 + sel) * B_ + batch) * ((size_t)H_ * TP_ * DH_);
        kbase = split * (D_ / NSPLIT);
        NK = (D_ / NSPLIT) / 16;
    }

    // per-thread load assignment: 512 cp.async16 per stage, 2 per thread
    const __half* srcb[2];
    {
        int r0 = (tid >> 1) & 127;
        size_t arow;
        if (MODE == 0) arow = (size_t)(bm + r0);
        else arow = (size_t)batch * TP_ + g_act[batch * TP_ + bm + r0];
        size_t wrow = (size_t)(bn + r0);
        srcb[0] = A + arow * D_;
        srcb[1] = W + wrow * D_;
    }
    const int lc16 = (tid & 1) * 8;

    auto load_stage = [&](int kt, int stage) {
        const uint32_t dbase = sb + stage * STAGE_BYTES
                             + (((tid >> 1) & 127) * RS_) + (tid & 1) * 16;
        const int koff = kbase + kt * 16 + lc16;
        CP_ASYNC16(dbase, srcb[0] + koff);
        CP_ASYNC16(dbase + ARR_BYTES, srcb[1] + koff);
    };

    float acc[2][8][4];
    #pragma unroll
    for (int mt = 0; mt < 2; mt++)
        #pragma unroll
        for (int nt = 0; nt < 8; nt++)
            #pragma unroll
            for (int j = 0; j < 4; j++) acc[mt][nt][j] = 0.0f;

    const int wm = (wid & 3) * 32;
    const int wn = (wid >> 2) * 64;

    const int arow = (lane & 7) + ((lane >> 3) & 1) * 8;
    const int akh  = lane >> 4;
    const int brow = (lane & 7) + (lane >> 4) * 8;
    const int bkh  = (lane >> 3) & 1;
    const uint32_t aoff = (uint32_t)((wm + arow) * RS_ + akh * 16);
    const uint32_t boff = (uint32_t)(ARR_BYTES + (wn + brow) * RS_ + bkh * 16);

    // prologue: 3 stages in flight
    #pragma unroll
    for (int s = 0; s < NSTAGE - 1; s++) { load_stage(s, s); CP_COMMIT(); }

    for (int kt = 0; kt < NK; kt++) {
        asm volatile("cp.async.wait_group %0;" :: "n"(NSTAGE - 2) : "memory");
        __syncthreads();

        if (kt + NSTAGE - 1 < NK) load_stage(kt + NSTAGE - 1, (kt + NSTAGE - 1) & (NSTAGE - 1));
        CP_COMMIT();

        const uint32_t st = sb + (kt & (NSTAGE - 1)) * STAGE_BYTES;
        const uint32_t aB = st + aoff;
        const uint32_t bB = st + boff;

        uint32_t af[2][4];
        ldsm_x4(af[0], aB);
        ldsm_x4(af[1], aB + 16 * RS_);
        #pragma unroll
        for (int np = 0; np < 4; np++) {
            uint32_t bw[4];
            ldsm_x4(bw, bB + np * 16 * RS_);
            #pragma unroll
            for (int s = 0; s < 2; s++) {
                const int nt = 2 * np + s;
                #pragma unroll
                for (int mt = 0; mt < 2; mt++)
                    mma_f16(acc[mt][nt], af[mt][0], af[mt][1], af[mt][2], af[mt][3], bw[2*s], bw[2*s+1]);
            }
        }
    }

    // ---- epilogue ----
    const int lr = lane >> 2;
    const int lc = (lane & 3) * 2;
    #pragma unroll
    for (int nt = 0; nt < 8; nt++) {
        int c0 = bn + wn + (nt >> 1) * 16 + (nt & 1) * 8 + lc;
        int h = c0 >> 6, d0 = c0 & 63;
        float2 b2 = make_float2(0.0f, 0.0f);
        if (MODE == 0) b2 = *(const float2*)(bq_ + c0);
        #pragma unroll
        for (int mt = 0; mt < 2; mt++) {
            int m0 = bm + wm + mt * 16 + lr;
            #pragma unroll
            for (int half = 0; half < 2; half++) {
                int m = m0 + half * 8;
                size_t dst;
                if (MODE == 0) {
                    int b = m >> 12, ls = m & (T_ - 1);
                    dst = ((size_t)(b * H_ + h) * T_ + ls) * DH_ + d0;
                } else {
                    dst = ((size_t)h * TP_ + m) * DH_ + d0;
                }
                float2 o;
                o.x = acc[mt][nt][2 * half + 0] + b2.x;
                o.y = acc[mt][nt][2 * half + 1] + b2.y;
                *(float2*)(outp + dst) = o;
            }
        }
    }
}

// ---------------- 5) split-K reduce + bias for K/V ---------------------------
__global__ void kv_reduce_kernel(const float* __restrict__ bk,
                                 const float* __restrict__ bv) {
    int p = blockIdx.x * blockDim.x + threadIdx.x;  // float4 index
    int d4  = p & 15;
    int i   = (p >> 4) & (TP_ - 1);
    int h   = (p >> 14) & (H_ - 1);
    int b   = (p >> 18) & (B_ - 1);
    int sel = (p >> 19) & 1;
    if (i >= g_cnt[b]) return;
    float4 acc = make_float4(0.f, 0.f, 0.f, 0.f);
    #pragma unroll
    for (int sp = 0; sp < NSPLIT; sp++) {
        const float* base = g_KVp
            + ((size_t)(sp * 2 + sel) * B_ + b) * ((size_t)H_ * TP_ * DH_)
            + ((size_t)h * TP_ + i) * DH_;
        float4 v = ((const float4*)base)[d4];
        acc.x += v.x; acc.y += v.y; acc.z += v.z; acc.w += v.w;
    }
    const float* bias = sel ? bv : bk;
    float4 bb = ((const float4*)(bias + h * DH_))[d4];
    acc.x += bb.x; acc.y += bb.y; acc.z += bb.z; acc.w += bb.w;
    float* outp = sel ? g_V : g_K;
    ((float4*)(outp + ((size_t)(b * H_ + h) * TP_ + i) * DH_))[d4] = acc;
}

// ---------------- 6) attention over compacted keys (fp32 SIMT) --------------
__global__ void __launch_bounds__(256)
attn_kernel(float* __restrict__ out)
{
    __shared__ float Qs[64][68];
    __shared__ float Kst[64][34];
    __shared__ float Vs[32][68];
    __shared__ float Ps[64][33];

    const int b = blockIdx.z, h = blockIdx.y, q0 = blockIdx.x * 64;
    const int tid = threadIdx.x;
    const int tx = tid & 15, ty = tid >> 4;
    const int cnt = g_cnt[b];
    const int ntiles = (cnt + 31) >> 5;

    const float* Qg = g_Q + ((size_t)(b * H_ + h) * T_ + q0) * DH_;
    const float* Kg = g_K + ((size_t)(b * H_ + h) * TP_) * DH_;
    const float* Vg = g_V + ((size_t)(b * H_ + h) * TP_) * DH_;

    for (int idx = tid; idx < 64 * 16; idx += 256) {
        int r = idx >> 4, c4 = (idx & 15) * 4;
        float4 v = *(const float4*)(Qg + (size_t)r * DH_ + c4);
        v.x *= 0.125f; v.y *= 0.125f; v.z *= 0.125f; v.w *= 0.125f;
        *(float4*)&Qs[r][c4] = v;
    }

    float acc[4][4];
    #pragma unroll
    for (int i = 0; i < 4; i++)
        #pragma unroll
        for (int j = 0; j < 4; j++) acc[i][j] = 0.0f;
    float mrow[4], lrow[4];
    #pragma unroll
    for (int i = 0; i < 4; i++) { mrow[i] = -1e30f; lrow[i] = 0.0f; }

    for (int t = 0; t < ntiles; t++) {
        const int kb = t * 32;
        __syncthreads();
        for (int idx = tid; idx < 512; idx += 256) {
            int c4 = idx >> 5, key = idx & 31;
            float4 v = *(const float4*)(Kg + (size_t)(kb + key) * DH_ + c4 * 4);
            Kst[c4 * 4 + 0][key] = v.x;
            Kst[c4 * 4 + 1][key] = v.y;
            Kst[c4 * 4 + 2][key] = v.z;
            Kst[c4 * 4 + 3][key] = v.w;
        }
        for (int idx = tid; idx < 512; idx += 256) {
            int r = idx >> 4, c4 = (idx & 15) * 4;
            *(float4*)&Vs[r][c4] = *(const float4*)(Vg + (size_t)(kb + r) * DH_ + c4);
        }
        __syncthreads();

        float s[4][2];
        #pragma unroll
        for (int i = 0; i < 4; i++) { s[i][0] = 0.0f; s[i][1] = 0.0f; }
        #pragma unroll
        for (int d = 0; d < 64; d++) {
            float2 bk2 = *(const float2*)&Kst[d][2 * tx];
            #pragma unroll
            for (int i = 0; i < 4; i++) {
                float a = Qs[4 * ty + i][d];
                s[i][0] = fmaf(a, bk2.x, s[i][0]);
                s[i][1] = fmaf(a, bk2.y, s[i][1]);
            }
        }
        #pragma unroll
        for (int j = 0; j < 2; j++)
            if (kb + 2 * tx + j >= cnt) {
                #pragma unroll
                for (int i = 0; i < 4; i++) s[i][j] = -1e30f;
            }

        #pragma unroll
        for (int i = 0; i < 4; i++) {
            float tm = fmaxf(s[i][0], s[i][1]);
            #pragma unroll
            for (int off = 8; off >= 1; off >>= 1)
                tm = fmaxf(tm, __shfl_xor_sync(0xffffffffu, tm, off));
            float mn = fmaxf(mrow[i], tm);
            float p0 = __expf(s[i][0] - mn);
            float p1 = __expf(s[i][1] - mn);
            Ps[4 * ty + i][2 * tx]     = p0;
            Ps[4 * ty + i][2 * tx + 1] = p1;
            float ts = p0 + p1;
            #pragma unroll
            for (int off = 8; off >= 1; off >>= 1)
                ts += __shfl_xor_sync(0xffffffffu, ts, off);
            float alpha = __expf(mrow[i] - mn);
            lrow[i] = lrow[i] * alpha + ts;
            mrow[i] = mn;
            #pragma unroll
            for (int j = 0; j < 4; j++) acc[i][j] *= alpha;
        }
        __syncwarp();

        #pragma unroll
        for (int kk = 0; kk < 32; kk++) {
            float v4[4];
            *(float4*)v4 = *(const float4*)&Vs[kk][4 * tx];
            #pragma unroll
            for (int i = 0; i < 4; i++) {
                float p = Ps[4 * ty + i][kk];
                #pragma unroll
                for (int j = 0; j < 4; j++)
                    acc[i][j] = fmaf(p, v4[j], acc[i][j]);
            }
        }
    }

    #pragma unroll
    for (int i = 0; i < 4; i++) {
        int row = 4 * ty + i;
        float inv = 1.0f / lrow[i];
        float4 r;
        r.x = acc[i][0] * inv; r.y = acc[i][1] * inv;
        r.z = acc[i][2] * inv; r.w = acc[i][3] * inv;
        *(float4*)(out + ((size_t)(b * T_ + q0 + row)) * D_ + h * DH_ + 4 * tx) = r;
    }
}

// ---------------- launch -----------------------------------------------------
extern "C" void kernel_launch(void* const* d_in, const int* in_sizes, int n_in,
                              void* d_out, int out_size) {
    const float* hs = (const float*)d_in[0];
    const int*   am = (const int*)d_in[1];
    const float* Wq = (const float*)d_in[2];
    const float* bq = (const float*)d_in[3];
    const float* Wk = (const float*)d_in[4];
    const float* bk = (const float*)d_in[5];
    const float* Wv = (const float*)d_in[6];
    const float* bv = (const float*)d_in[7];
    float* out = (float*)d_out;

    cudaFuncSetAttribute(gemm_mma_kernel<0>, cudaFuncAttributeMaxDynamicSharedMemorySize, SMEM_GEMM);
    cudaFuncSetAttribute(gemm_mma_kernel<1>, cudaFuncAttributeMaxDynamicSharedMemorySize, SMEM_GEMM);

    wconv_kernel<<<3 * W4_ / 256, 256>>>(Wq, Wk, Wv);
    hs_pool_kernel<<<(B_ * TP_ * D_ / 4) / 256, 256>>>(hs);
    mask_kernel<<<B_, TP_>>>(am);
    gemm_mma_kernel<0><<<dim3(D_ / 128, (B_ * T_) / 128, 1), 256, SMEM_GEMM>>>(bq);
    gemm_mma_kernel<1><<<dim3(D_ / 128, TP_ / 128, 4 * NSPLIT), 256, SMEM_GEMM>>>(nullptr);
    kv_reduce_kernel<<<(2 * B_ * H_ * TP_ * (DH_ / 4)) / 256, 256>>>(bk, bv);
    attn_kernel<<<dim3(T_ / 64, H_, B_), 256>>>(out);
}

// round 10
// speedup vs baseline: 4.2543x; 1.3109x over previous
#include <cuda_runtime.h>
#include <cuda_fp16.h>
#include <cstdint>

#define B_  2
#define T_  4096
#define D_  1024
#define H_  16
#define DH_ 64
#define KP_ 4
#define TP_ 1024
#define NSPLIT 4

// ---------------- scratch (device globals; no allocations allowed) ----------
__device__ __half g_hs[(size_t)B_ * T_ * D_];
__device__ __half g_pool[B_ * TP_ * D_];
__device__ __half g_Wq[D_ * D_], g_Wk[D_ * D_], g_Wv[D_ * D_];
__device__ __half g_Qhi[(size_t)B_ * H_ * T_ * DH_];   // [B,H,T,DH], pre-scaled 1/8
__device__ __half g_Qlo[(size_t)B_ * H_ * T_ * DH_];
__device__ __half g_Khi[(size_t)B_ * H_ * TP_ * DH_];  // rows >= cnt zero-filled
__device__ __half g_Klo[(size_t)B_ * H_ * TP_ * DH_];
__device__ __half g_Vhi[(size_t)B_ * H_ * TP_ * DH_];
__device__ __half g_Vlo[(size_t)B_ * H_ * TP_ * DH_];
// split-K partials: [split][sel][batch][H][TP][DH]
__device__ float g_KVp[(size_t)NSPLIT * 2 * B_ * H_ * TP_ * DH_];
__device__ int   g_act[B_ * TP_];
__device__ int   g_cnt[B_];

// ---------------- helpers ----------------------------------------------------
__device__ __forceinline__ uint32_t smem_u32(const void* p) {
    uint32_t a;
    asm("{ .reg .u64 t; cvta.to.shared.u64 t, %1; cvt.u32.u64 %0, t; }" : "=r"(a) : "l"(p));
    return a;
}
#define CP_ASYNC16(dst, src) \
    asm volatile("cp.async.cg.shared.global [%0], [%1], 16;" :: "r"(dst), "l"(src))
#define CP_COMMIT() asm volatile("cp.async.commit_group;" ::: "memory")

__device__ __forceinline__ void mma_f16(float* c,
        uint32_t a0, uint32_t a1, uint32_t a2, uint32_t a3,
        uint32_t b0, uint32_t b1) {
    asm volatile("mma.sync.aligned.m16n8k16.row.col.f32.f16.f16.f32 "
        "{%0,%1,%2,%3}, {%4,%5,%6,%7}, {%8,%9}, {%0,%1,%2,%3};"
        : "+f"(c[0]), "+f"(c[1]), "+f"(c[2]), "+f"(c[3])
        : "r"(a0), "r"(a1), "r"(a2), "r"(a3), "r"(b0), "r"(b1));
}
__device__ __forceinline__ void ldsm_x4(uint32_t* r, uint32_t addr) {
    asm volatile("ldmatrix.sync.aligned.m8n8.x4.shared.b16 {%0,%1,%2,%3}, [%4];"
        : "=r"(r[0]), "=r"(r[1]), "=r"(r[2]), "=r"(r[3]) : "r"(addr));
}
__device__ __forceinline__ void ldsm_x4t(uint32_t* r, uint32_t addr) {
    asm volatile("ldmatrix.sync.aligned.m8n8.x4.trans.shared.b16 {%0,%1,%2,%3}, [%4];"
        : "=r"(r[0]), "=r"(r[1]), "=r"(r[2]), "=r"(r[3]) : "r"(addr));
}
__device__ __forceinline__ uint32_t packh2(__half x, __half y) {
    __half2 v = __halves2half2(x, y);
    return *(uint32_t*)&v;
}

// ---------------- 1) weight fp16 conversion ----------------------------------
#define W4_ (D_ * D_ / 4)
__global__ void wconv_kernel(const float* __restrict__ Wq,
                             const float* __restrict__ Wk,
                             const float* __restrict__ Wv) {
    int p = blockIdx.x * blockDim.x + threadIdx.x;
    const float* src;
    __half* dst;
    int seg = p / W4_, off = p - seg * W4_;
    if (seg == 0)      { src = Wq; dst = g_Wq; }
    else if (seg == 1) { src = Wk; dst = g_Wk; }
    else               { src = Wv; dst = g_Wv; }
    float4 v = ((const float4*)src)[off];
    ushort4 h;
    h.x = __half_as_ushort(__float2half_rn(v.x));
    h.y = __half_as_ushort(__float2half_rn(v.y));
    h.z = __half_as_ushort(__float2half_rn(v.z));
    h.w = __half_as_ushort(__float2half_rn(v.w));
    ((ushort4*)dst)[off] = h;
}

// ---------------- 2) hs fp16 + avgpool fp16 ----------------------------------
__global__ void hs_pool_kernel(const float* __restrict__ hs) {
    int p = blockIdx.x * blockDim.x + threadIdx.x;
    int d4  = p & 255;
    int row = p >> 8;
    const float4* src = (const float4*)hs;
    size_t base = (size_t)row * (KP_ * 256) + d4;
    float4 s[4];
    #pragma unroll
    for (int r = 0; r < 4; r++) s[r] = src[base + r * 256];
    #pragma unroll
    for (int r = 0; r < 4; r++) {
        ushort4 h;
        h.x = __half_as_ushort(__float2half_rn(s[r].x));
        h.y = __half_as_ushort(__float2half_rn(s[r].y));
        h.z = __half_as_ushort(__float2half_rn(s[r].z));
        h.w = __half_as_ushort(__float2half_rn(s[r].w));
        ((ushort4*)g_hs)[base + r * 256] = h;
    }
    ushort4 h;
    h.x = __half_as_ushort(__float2half_rn((s[0].x + s[1].x + s[2].x + s[3].x) * 0.25f));
    h.y = __half_as_ushort(__float2half_rn((s[0].y + s[1].y + s[2].y + s[3].y) * 0.25f));
    h.z = __half_as_ushort(__float2half_rn((s[0].z + s[1].z + s[2].z + s[3].z) * 0.25f));
    h.w = __half_as_ushort(__float2half_rn((s[0].w + s[1].w + s[2].w + s[3].w) * 0.25f));
    ((ushort4*)g_pool)[p] = h;
}

// ---------------- 3) mask -> compacted active-key list ----------------------
__global__ void mask_kernel(const int* __restrict__ am) {
    __shared__ int sc[TP_];
    int b = blockIdx.x, tt = threadIdx.x;
    const int* m = am + b * T_ + tt * KP_;
    int s = m[0] + m[1] + m[2] + m[3];
    int act = (s == 0) ? 1 : 0;
    sc[tt] = act;
    __syncthreads();
    for (int off = 1; off < TP_; off <<= 1) {
        int v = 0;
        if (tt >= off) v = sc[tt - off];
        __syncthreads();
        sc[tt] += v;
        __syncthreads();
    }
    int total = sc[TP_ - 1];
    if (total == 0) {
        g_act[b * TP_ + tt] = tt;
        if (tt == 0) g_cnt[b] = TP_;
    } else {
        if (act) g_act[b * TP_ + sc[tt] - 1] = tt;
        if (tt >= total) g_act[b * TP_ + tt] = 0;
        if (tt == 0) g_cnt[b] = total;
    }
}

// ---------------- 4) mma.sync fp16 projection GEMM ---------------------------
#define RS_ 48
#define ARR_BYTES (128 * RS_)
#define STAGE_BYTES (2 * ARR_BYTES)
#define NSTAGE 4
#define SMEM_GEMM (NSTAGE * STAGE_BYTES)  // 49152

template<int MODE>
__global__ void __launch_bounds__(256, 2)
gemm_mma_kernel(const float* __restrict__ bq_)
{
    extern __shared__ char smc[];
    const uint32_t sb = smem_u32(smc);
    const int tid = threadIdx.x;
    const int wid = tid >> 5, lane = tid & 31;
    const int bn = blockIdx.x * 128;
    const int bm = blockIdx.y * 128;

    const __half *A, *W;
    float* outp = nullptr;
    int batch = 0, kbase = 0, NK;
    if (MODE == 0) {
        A = g_hs; W = g_Wq;
        NK = D_ / 16;
    } else {
        int z = blockIdx.z;
        batch = z & 1;
        int sel = (z >> 1) & 1;
        int split = z >> 2;
        if (bm >= g_cnt[batch]) return;
        A = g_pool;
        W = sel ? g_Wv : g_Wk;
        outp = g_KVp + ((size_t)(split * 2 + sel) * B_ + batch) * ((size_t)H_ * TP_ * DH_);
        kbase = split * (D_ / NSPLIT);
        NK = (D_ / NSPLIT) / 16;
    }

    const __half* srcb[2];
    {
        int r0 = (tid >> 1) & 127;
        size_t arow;
        if (MODE == 0) arow = (size_t)(bm + r0);
        else arow = (size_t)batch * TP_ + g_act[batch * TP_ + bm + r0];
        size_t wrow = (size_t)(bn + r0);
        srcb[0] = A + arow * D_;
        srcb[1] = W + wrow * D_;
    }
    const int lc16 = (tid & 1) * 8;

    auto load_stage = [&](int kt, int stage) {
        const uint32_t dbase = sb + stage * STAGE_BYTES
                             + (((tid >> 1) & 127) * RS_) + (tid & 1) * 16;
        const int koff = kbase + kt * 16 + lc16;
        CP_ASYNC16(dbase, srcb[0] + koff);
        CP_ASYNC16(dbase + ARR_BYTES, srcb[1] + koff);
    };

    float acc[2][8][4];
    #pragma unroll
    for (int mt = 0; mt < 2; mt++)
        #pragma unroll
        for (int nt = 0; nt < 8; nt++)
            #pragma unroll
            for (int j = 0; j < 4; j++) acc[mt][nt][j] = 0.0f;

    const int wm = (wid & 3) * 32;
    const int wn = (wid >> 2) * 64;

    const int arow = (lane & 7) + ((lane >> 3) & 1) * 8;
    const int akh  = lane >> 4;
    const int brow = (lane & 7) + (lane >> 4) * 8;
    const int bkh  = (lane >> 3) & 1;
    const uint32_t aoff = (uint32_t)((wm + arow) * RS_ + akh * 16);
    const uint32_t boff = (uint32_t)(ARR_BYTES + (wn + brow) * RS_ + bkh * 16);

    #pragma unroll
    for (int s = 0; s < NSTAGE - 1; s++) { load_stage(s, s); CP_COMMIT(); }

    for (int kt = 0; kt < NK; kt++) {
        asm volatile("cp.async.wait_group %0;" :: "n"(NSTAGE - 2) : "memory");
        __syncthreads();

        if (kt + NSTAGE - 1 < NK) load_stage(kt + NSTAGE - 1, (kt + NSTAGE - 1) & (NSTAGE - 1));
        CP_COMMIT();

        const uint32_t st = sb + (kt & (NSTAGE - 1)) * STAGE_BYTES;
        const uint32_t aB = st + aoff;
        const uint32_t bB = st + boff;

        uint32_t af[2][4];
        ldsm_x4(af[0], aB);
        ldsm_x4(af[1], aB + 16 * RS_);
        #pragma unroll
        for (int np = 0; np < 4; np++) {
            uint32_t bw[4];
            ldsm_x4(bw, bB + np * 16 * RS_);
            #pragma unroll
            for (int s = 0; s < 2; s++) {
                const int nt = 2 * np + s;
                #pragma unroll
                for (int mt = 0; mt < 2; mt++)
                    mma_f16(acc[mt][nt], af[mt][0], af[mt][1], af[mt][2], af[mt][3], bw[2*s], bw[2*s+1]);
            }
        }
    }

    // ---- epilogue ----
    const int lr = lane >> 2;
    const int lc = (lane & 3) * 2;
    #pragma unroll
    for (int nt = 0; nt < 8; nt++) {
        int c0 = bn + wn + (nt >> 1) * 16 + (nt & 1) * 8 + lc;
        int h = c0 >> 6, d0 = c0 & 63;
        float2 b2 = make_float2(0.0f, 0.0f);
        if (MODE == 0) b2 = *(const float2*)(bq_ + c0);
        #pragma unroll
        for (int mt = 0; mt < 2; mt++) {
            int m0 = bm + wm + mt * 16 + lr;
            #pragma unroll
            for (int half = 0; half < 2; half++) {
                int m = m0 + half * 8;
                if (MODE == 0) {
                    int b = m >> 12, ls = m & (T_ - 1);
                    size_t dst = ((size_t)(b * H_ + h) * T_ + ls) * DH_ + d0;
                    float sx = (acc[mt][nt][2 * half + 0] + b2.x) * 0.125f;
                    float sy = (acc[mt][nt][2 * half + 1] + b2.y) * 0.125f;
                    __half hx = __float2half_rn(sx), hy = __float2half_rn(sy);
                    __half lx = __float2half_rn(sx - __half2float(hx));
                    __half ly = __float2half_rn(sy - __half2float(hy));
                    *(uint32_t*)(g_Qhi + dst) = packh2(hx, hy);
                    *(uint32_t*)(g_Qlo + dst) = packh2(lx, ly);
                } else {
                    size_t dst = ((size_t)h * TP_ + m) * DH_ + d0;
                    float2 o;
                    o.x = acc[mt][nt][2 * half + 0];
                    o.y = acc[mt][nt][2 * half + 1];
                    *(float2*)(outp + dst) = o;
                }
            }
        }
    }
}

// ---------------- 5) split-K reduce + bias -> K/V fp16 hi/lo -----------------
__global__ void kv_reduce_kernel(const float* __restrict__ bk,
                                 const float* __restrict__ bv) {
    int p = blockIdx.x * blockDim.x + threadIdx.x;  // 4-elem group index
    int d4  = p & 15;
    int i   = (p >> 4) & (TP_ - 1);
    int h   = (p >> 14) & (H_ - 1);
    int b   = (p >> 18) & (B_ - 1);
    int sel = (p >> 19) & 1;
    size_t dsti = ((size_t)(b * H_ + h) * TP_ + i) * DH_ + d4 * 4;
    __half* outh = sel ? g_Vhi : g_Khi;
    __half* outl = sel ? g_Vlo : g_Klo;
    if (i >= g_cnt[b]) {
        // zero-fill so P@V never multiplies garbage (0 * p=0 stays 0)
        *(uint2*)(outh + dsti) = make_uint2(0u, 0u);
        *(uint2*)(outl + dsti) = make_uint2(0u, 0u);
        return;
    }
    float4 acc = make_float4(0.f, 0.f, 0.f, 0.f);
    #pragma unroll
    for (int sp = 0; sp < NSPLIT; sp++) {
        const float* base = g_KVp
            + ((size_t)(sp * 2 + sel) * B_ + b) * ((size_t)H_ * TP_ * DH_)
            + ((size_t)h * TP_ + i) * DH_;
        float4 v = ((const float4*)base)[d4];
        acc.x += v.x; acc.y += v.y; acc.z += v.z; acc.w += v.w;
    }
    const float* bias = sel ? bv : bk;
    float4 bb = ((const float4*)(bias + h * DH_))[d4];
    acc.x += bb.x; acc.y += bb.y; acc.z += bb.z; acc.w += bb.w;
    __half hx = __float2half_rn(acc.x), hy = __float2half_rn(acc.y);
    __half hz = __float2half_rn(acc.z), hw = __float2half_rn(acc.w);
    uint2 hv, lv;
    hv.x = packh2(hx, hy); hv.y = packh2(hz, hw);
    lv.x = packh2(__float2half_rn(acc.x - __half2float(hx)),
                  __float2half_rn(acc.y - __half2float(hy)));
    lv.y = packh2(__float2half_rn(acc.z - __half2float(hz)),
                  __float2half_rn(acc.w - __half2float(hw)));
    *(uint2*)(outh + dsti) = hv;
    *(uint2*)(outl + dsti) = lv;
}

// ---------------- 6) fp16 tensor-core flash attention ------------------------
// Block: 64 q x 64-key tiles, 4 warps (16 q each). hi/lo 3-pass everywhere.
// smem arrays [64][64] fp16, row stride 144B (16B-aligned, conflict-free).
#define ATS 144
#define AARR (64 * ATS)      // 9216
#define SM_QH 0
#define SM_QL (AARR)
#define SM_KH (2 * AARR)
#define SM_KL (3 * AARR)
#define SM_VH (4 * AARR)
#define SM_VL (5 * AARR)
#define SMEM_ATTN (6 * AARR) // 55296

__global__ void __launch_bounds__(128, 4)
attn_kernel(float* __restrict__ out)
{
    extern __shared__ char smc[];
    const uint32_t sb = smem_u32(smc);
    const int tid = threadIdx.x, wid = tid >> 5, lane = tid & 31;
    const int b = blockIdx.z, h = blockIdx.y, q0 = blockIdx.x * 64;
    const int cnt = g_cnt[b];
    const int ntiles = (cnt + 63) >> 6;

    const __half* Qhp = g_Qhi + ((size_t)(b * H_ + h) * T_ + q0) * DH_;
    const __half* Qlp = g_Qlo + ((size_t)(b * H_ + h) * T_ + q0) * DH_;
    const size_t kvoff = (size_t)(b * H_ + h) * TP_ * DH_;
    const __half* kvsrc[4] = { g_Khi + kvoff, g_Klo + kvoff,
                               g_Vhi + kvoff, g_Vlo + kvoff };

    // load Q tiles (2 arrays x 64 rows x 128B = 1024 chunks)
    #pragma unroll
    for (int i = 0; i < 8; i++) {
        int idx = tid + i * 128;
        int arr = idx >> 9, r = (idx >> 3) & 63, c = idx & 7;
        const __half* src = (arr ? Qlp : Qhp) + (size_t)r * DH_ + c * 8;
        CP_ASYNC16(sb + arr * AARR + r * ATS + c * 16, src);
    }
    CP_COMMIT();

    float acc[8][4];
    #pragma unroll
    for (int nt = 0; nt < 8; nt++)
        #pragma unroll
        for (int j = 0; j < 4; j++) acc[nt][j] = 0.0f;
    float mrow[2] = { -1e30f, -1e30f };
    float lrow[2] = { 0.0f, 0.0f };

    const int lr = lane >> 2, lq = lane & 3;
    const int arow = (lane & 7) + ((lane >> 3) & 1) * 8;
    const int akh  = lane >> 4;
    const int brow = (lane & 7) + (lane >> 4) * 8;
    const int bkh  = (lane >> 3) & 1;
    const int vrow = (lane & 7) + ((lane >> 3) & 1) * 8;
    const int vc16 = (lane >> 4) * 16;

    const uint32_t qbase = sb + SM_QH + (wid * 16 + arow) * ATS + akh * 16;
    const uint32_t kbase = sb + SM_KH + brow * ATS + bkh * 16;
    const uint32_t vbase = sb + SM_VH + vrow * ATS + vc16;

    for (int t = 0; t < ntiles; t++) {
        const int kb = t * 64;
        // load K/V tiles (4 arrays x 512 chunks)
        #pragma unroll
        for (int i = 0; i < 16; i++) {
            int idx = tid + i * 128;
            int arr = idx >> 9, r = (idx >> 3) & 63, c = idx & 7;
            CP_ASYNC16(sb + SM_KH + arr * AARR + r * ATS + c * 16,
                       kvsrc[arr] + (size_t)(kb + r) * DH_ + c * 8);
        }
        CP_COMMIT();
        asm volatile("cp.async.wait_group 0;" ::: "memory");
        __syncthreads();

        // ---- scores: 3-pass QhKh + QhKl + QlKh ----
        float sc[8][4];
        #pragma unroll
        for (int nt = 0; nt < 8; nt++)
            #pragma unroll
            for (int j = 0; j < 4; j++) sc[nt][j] = 0.0f;
        #pragma unroll
        for (int j = 0; j < 4; j++) {          // dh k16 chunks
            uint32_t qh[4], ql[4];
            ldsm_x4(qh, qbase + j * 32);
            ldsm_x4(ql, qbase + AARR + j * 32);
            #pragma unroll
            for (int np = 0; np < 4; np++) {   // key 16-pairs
                uint32_t kh4[4], kl4[4];
                ldsm_x4(kh4, kbase + np * 16 * ATS + j * 32);
                ldsm_x4(kl4, kbase + AARR + np * 16 * ATS + j * 32);
                #pragma unroll
                for (int s = 0; s < 2; s++) {
                    const int nt = 2 * np + s;
                    mma_f16(sc[nt], qh[0], qh[1], qh[2], qh[3], kh4[2*s], kh4[2*s+1]);
                    mma_f16(sc[nt], qh[0], qh[1], qh[2], qh[3], kl4[2*s], kl4[2*s+1]);
                    mma_f16(sc[nt], ql[0], ql[1], ql[2], ql[3], kh4[2*s], kh4[2*s+1]);
                }
            }
        }

        // ---- mask tail keys ----
        #pragma unroll
        for (int nt = 0; nt < 8; nt++) {
            int key = kb + nt * 8 + lq * 2;
            if (key >= cnt)     { sc[nt][0] = -1e30f; sc[nt][2] = -1e30f; }
            if (key + 1 >= cnt) { sc[nt][1] = -1e30f; sc[nt][3] = -1e30f; }
        }

        // ---- online softmax (rows lr and lr+8; quad-replicated stats) ----
        float tm0 = -1e30f, tm1 = -1e30f;
        #pragma unroll
        for (int nt = 0; nt < 8; nt++) {
            tm0 = fmaxf(tm0, fmaxf(sc[nt][0], sc[nt][1]));
            tm1 = fmaxf(tm1, fmaxf(sc[nt][2], sc[nt][3]));
        }
        tm0 = fmaxf(tm0, __shfl_xor_sync(0xffffffffu, tm0, 1));
        tm0 = fmaxf(tm0, __shfl_xor_sync(0xffffffffu, tm0, 2));
        tm1 = fmaxf(tm1, __shfl_xor_sync(0xffffffffu, tm1, 1));
        tm1 = fmaxf(tm1, __shfl_xor_sync(0xffffffffu, tm1, 2));
        const float mn0 = fmaxf(mrow[0], tm0);
        const float mn1 = fmaxf(mrow[1], tm1);
        const float al0 = __expf(mrow[0] - mn0);
        const float al1 = __expf(mrow[1] - mn1);

        uint32_t pAh[4][4], pAl[4][4];
        float ts0 = 0.0f, ts1 = 0.0f;
        #pragma unroll
        for (int nt = 0; nt < 8; nt++) {
            float p0 = __expf(sc[nt][0] - mn0);
            float p1 = __expf(sc[nt][1] - mn0);
            float p2 = __expf(sc[nt][2] - mn1);
            float p3 = __expf(sc[nt][3] - mn1);
            ts0 += p0 + p1;
            ts1 += p2 + p3;
            __half h0 = __float2half_rn(p0), h1 = __float2half_rn(p1);
            __half h2 = __float2half_rn(p2), h3 = __float2half_rn(p3);
            __half e0 = __float2half_rn(p0 - __half2float(h0));
            __half e1 = __float2half_rn(p1 - __half2float(h1));
            __half e2 = __float2half_rn(p2 - __half2float(h2));
            __half e3 = __float2half_rn(p3 - __half2float(h3));
            const int j = nt >> 1, o = (nt & 1) * 2;
            pAh[j][o]     = packh2(h0, h1);
            pAh[j][o + 1] = packh2(h2, h3);
            pAl[j][o]     = packh2(e0, e1);
            pAl[j][o + 1] = packh2(e2, e3);
        }
        ts0 += __shfl_xor_sync(0xffffffffu, ts0, 1);
        ts0 += __shfl_xor_sync(0xffffffffu, ts0, 2);
        ts1 += __shfl_xor_sync(0xffffffffu, ts1, 1);
        ts1 += __shfl_xor_sync(0xffffffffu, ts1, 2);
        lrow[0] = lrow[0] * al0 + ts0;
        lrow[1] = lrow[1] * al1 + ts1;
        mrow[0] = mn0;
        mrow[1] = mn1;
        #pragma unroll
        for (int nt = 0; nt < 8; nt++) {
            acc[nt][0] *= al0; acc[nt][1] *= al0;
            acc[nt][2] *= al1; acc[nt][3] *= al1;
        }

        // ---- P @ V : 3-pass PhVh + PhVl + PlVh ----
        #pragma unroll
        for (int j = 0; j < 4; j++) {          // key k16 chunks
            #pragma unroll
            for (int np = 0; np < 4; np++) {   // dh 16-pairs
                uint32_t vh4[4], vl4[4];
                ldsm_x4t(vh4, vbase + (j * 16) * ATS + np * 32);
                ldsm_x4t(vl4, vbase + AARR + (j * 16) * ATS + np * 32);
                #pragma unroll
                for (int s = 0; s < 2; s++) {
                    const int nt = 2 * np + s;
                    mma_f16(acc[nt], pAh[j][0], pAh[j][1], pAh[j][2], pAh[j][3], vh4[2*s], vh4[2*s+1]);
                    mma_f16(acc[nt], pAh[j][0], pAh[j][1], pAh[j][2], pAh[j][3], vl4[2*s], vl4[2*s+1]);
                    mma_f16(acc[nt], pAl[j][0], pAl[j][1], pAl[j][2], pAl[j][3], vh4[2*s], vh4[2*s+1]);
                }
            }
        }
        __syncthreads();   // done reading K/V smem before next tile overwrites
    }

    // ---- epilogue: divide by l, write [B, T, H*DH] ----
    const float inv0 = 1.0f / lrow[0];
    const float inv1 = 1.0f / lrow[1];
    const int row0 = q0 + wid * 16 + lr;
    #pragma unroll
    for (int nt = 0; nt < 8; nt++) {
        int dh = nt * 8 + lq * 2;
        float2 o;
        o.x = acc[nt][0] * inv0; o.y = acc[nt][1] * inv0;
        *(float2*)(out + ((size_t)b * T_ + row0) * D_ + h * DH_ + dh) = o;
        o.x = acc[nt][2] * inv1; o.y = acc[nt][3] * inv1;
        *(float2*)(out + ((size_t)b * T_ + row0 + 8) * D_ + h * DH_ + dh) = o;
    }
}

// ---------------- launch -----------------------------------------------------
extern "C" void kernel_launch(void* const* d_in, const int* in_sizes, int n_in,
                              void* d_out, int out_size) {
    const float* hs = (const float*)d_in[0];
    const int*   am = (const int*)d_in[1];
    const float* Wq = (const float*)d_in[2];
    const float* bq = (const float*)d_in[3];
    const float* Wk = (const float*)d_in[4];
    const float* bk = (const float*)d_in[5];
    const float* Wv = (const float*)d_in[6];
    const float* bv = (const float*)d_in[7];
    float* out = (float*)d_out;

    cudaFuncSetAttribute(gemm_mma_kernel<0>, cudaFuncAttributeMaxDynamicSharedMemorySize, SMEM_GEMM);
    cudaFuncSetAttribute(gemm_mma_kernel<1>, cudaFuncAttributeMaxDynamicSharedMemorySize, SMEM_GEMM);
    cudaFuncSetAttribute(attn_kernel, cudaFuncAttributeMaxDynamicSharedMemorySize, SMEM_ATTN);

    wconv_kernel<<<3 * W4_ / 256, 256>>>(Wq, Wk, Wv);
    hs_pool_kernel<<<(B_ * TP_ * D_ / 4) / 256, 256>>>(hs);
    mask_kernel<<<B_, TP_>>>(am);
    gemm_mma_kernel<0><<<dim3(D_ / 128, (B_ * T_) / 128, 1), 256, SMEM_GEMM>>>(bq);
    gemm_mma_kernel<1><<<dim3(D_ / 128, TP_ / 128, 4 * NSPLIT), 256, SMEM_GEMM>>>(nullptr);
    kv_reduce_kernel<<<(2 * B_ * H_ * TP_ * (DH_ / 4)) / 256, 256>>>(bk, bv);
    attn_kernel<<<dim3(T_ / 64, H_, B_), 128, SMEM_ATTN>>>(out);
}

// round 12
// speedup vs baseline: 5.2923x; 1.2440x over previous
#include <cuda_runtime.h>
#include <cuda_fp16.h>
#include <cstdint>

#define B_  2
#define T_  4096
#define D_  1024
#define H_  16
#define DH_ 64
#define KP_ 4
#define TP_ 1024
#define NSPLIT 4

// ---------------- scratch (device globals; no allocations allowed) ----------
__device__ __half g_hs[(size_t)B_ * T_ * D_];
__device__ __half g_pool[B_ * TP_ * D_];
__device__ __half g_Wq[D_ * D_], g_Wk[D_ * D_], g_Wv[D_ * D_];
__device__ __half g_Qhi[(size_t)B_ * H_ * T_ * DH_];   // [B,H,T,DH], pre-scaled 1/8
__device__ __half g_Qlo[(size_t)B_ * H_ * T_ * DH_];
__device__ __half g_Khi[(size_t)B_ * H_ * TP_ * DH_];  // rows >= cnt zero-filled
__device__ __half g_Klo[(size_t)B_ * H_ * TP_ * DH_];
__device__ __half g_Vhi[(size_t)B_ * H_ * TP_ * DH_];
__device__ __half g_Vlo[(size_t)B_ * H_ * TP_ * DH_];
__device__ float g_KVp[(size_t)NSPLIT * 2 * B_ * H_ * TP_ * DH_];
__device__ int   g_act[B_ * TP_];
__device__ int   g_cnt[B_];

// ---------------- helpers ----------------------------------------------------
__device__ __forceinline__ uint32_t smem_u32(const void* p) {
    uint32_t a;
    asm("{ .reg .u64 t; cvta.to.shared.u64 t, %1; cvt.u32.u64 %0, t; }" : "=r"(a) : "l"(p));
    return a;
}
#define CP_ASYNC16(dst, src) \
    asm volatile("cp.async.cg.shared.global [%0], [%1], 16;" :: "r"(dst), "l"(src))
#define CP_COMMIT() asm volatile("cp.async.commit_group;" ::: "memory")

__device__ __forceinline__ void mma_f16(float* c,
        uint32_t a0, uint32_t a1, uint32_t a2, uint32_t a3,
        uint32_t b0, uint32_t b1) {
    asm volatile("mma.sync.aligned.m16n8k16.row.col.f32.f16.f16.f32 "
        "{%0,%1,%2,%3}, {%4,%5,%6,%7}, {%8,%9}, {%0,%1,%2,%3};"
        : "+f"(c[0]), "+f"(c[1]), "+f"(c[2]), "+f"(c[3])
        : "r"(a0), "r"(a1), "r"(a2), "r"(a3), "r"(b0), "r"(b1));
}
__device__ __forceinline__ void ldsm_x4(uint32_t* r, uint32_t addr) {
    asm volatile("ldmatrix.sync.aligned.m8n8.x4.shared.b16 {%0,%1,%2,%3}, [%4];"
        : "=r"(r[0]), "=r"(r[1]), "=r"(r[2]), "=r"(r[3]) : "r"(addr));
}
__device__ __forceinline__ void ldsm_x4t(uint32_t* r, uint32_t addr) {
    asm volatile("ldmatrix.sync.aligned.m8n8.x4.trans.shared.b16 {%0,%1,%2,%3}, [%4];"
        : "=r"(r[0]), "=r"(r[1]), "=r"(r[2]), "=r"(r[3]) : "r"(addr));
}
__device__ __forceinline__ uint32_t packh2(__half x, __half y) {
    __half2 v = __halves2half2(x, y);
    return *(uint32_t*)&v;
}

// ---------------- 1) fused weight fp16 conversion + hs/pool fp16 -------------
#define W4_ (D_ * D_ / 4)
#define HS4_ (B_ * TP_ * D_ / 4)
__global__ void prep_kernel(const float* __restrict__ hs,
                            const float* __restrict__ Wq,
                            const float* __restrict__ Wk,
                            const float* __restrict__ Wv) {
    int p = blockIdx.x * blockDim.x + threadIdx.x;
    if (p < 3 * W4_) {
        const float* src;
        __half* dst;
        int seg = p / W4_, off = p - seg * W4_;
        if (seg == 0)      { src = Wq; dst = g_Wq; }
        else if (seg == 1) { src = Wk; dst = g_Wk; }
        else               { src = Wv; dst = g_Wv; }
        float4 v = ((const float4*)src)[off];
        ushort4 h;
        h.x = __half_as_ushort(__float2half_rn(v.x));
        h.y = __half_as_ushort(__float2half_rn(v.y));
        h.z = __half_as_ushort(__float2half_rn(v.z));
        h.w = __half_as_ushort(__float2half_rn(v.w));
        ((ushort4*)dst)[off] = h;
        return;
    }
    p -= 3 * W4_;          // [0, HS4_)
    int d4  = p & 255;
    int row = p >> 8;
    const float4* src = (const float4*)hs;
    size_t base = (size_t)row * (KP_ * 256) + d4;
    float4 s[4];
    #pragma unroll
    for (int r = 0; r < 4; r++) s[r] = src[base + r * 256];
    #pragma unroll
    for (int r = 0; r < 4; r++) {
        ushort4 h;
        h.x = __half_as_ushort(__float2half_rn(s[r].x));
        h.y = __half_as_ushort(__float2half_rn(s[r].y));
        h.z = __half_as_ushort(__float2half_rn(s[r].z));
        h.w = __half_as_ushort(__float2half_rn(s[r].w));
        ((ushort4*)g_hs)[base + r * 256] = h;
    }
    ushort4 h;
    h.x = __half_as_ushort(__float2half_rn((s[0].x + s[1].x + s[2].x + s[3].x) * 0.25f));
    h.y = __half_as_ushort(__float2half_rn((s[0].y + s[1].y + s[2].y + s[3].y) * 0.25f));
    h.z = __half_as_ushort(__float2half_rn((s[0].z + s[1].z + s[2].z + s[3].z) * 0.25f));
    h.w = __half_as_ushort(__float2half_rn((s[0].w + s[1].w + s[2].w + s[3].w) * 0.25f));
    ((ushort4*)g_pool)[p] = h;
}

// ---------------- 2) mask -> compacted active-key list ----------------------
__global__ void mask_kernel(const int* __restrict__ am) {
    __shared__ int sc[TP_];
    int b = blockIdx.x, tt = threadIdx.x;
    const int* m = am + b * T_ + tt * KP_;
    int s = m[0] + m[1] + m[2] + m[3];
    int act = (s == 0) ? 1 : 0;
    sc[tt] = act;
    __syncthreads();
    for (int off = 1; off < TP_; off <<= 1) {
        int v = 0;
        if (tt >= off) v = sc[tt - off];
        __syncthreads();
        sc[tt] += v;
        __syncthreads();
    }
    int total = sc[TP_ - 1];
    if (total == 0) {
        g_act[b * TP_ + tt] = tt;
        if (tt == 0) g_cnt[b] = TP_;
    } else {
        if (act) g_act[b * TP_ + sc[tt] - 1] = tt;
        if (tt >= total) g_act[b * TP_ + tt] = 0;
        if (tt == 0) g_cnt[b] = total;
    }
}

// ---------------- 3) fused fp16 projection GEMM (Q + split-K KV) -------------
// k64 per stage, 2-stage cp.async, 64 HMMA per barrier window.
// Row stride 144B: 16B-aligned; ldmatrix 8-row phases hit banks 4r mod 32 - distinct.
// Flat grid: [0,512) = Q tiles; [512,1536) = KV (bn, bm, z) with early-exit.
#define RS_ 144
#define ARR_BYTES (128 * RS_)        // 18432
#define STAGE_BYTES (2 * ARR_BYTES)  // 36864
#define SMEM_GEMM (2 * STAGE_BYTES)  // 73728

__global__ void __launch_bounds__(256, 2)
gemm_fused_kernel(const float* __restrict__ bq_)
{
    extern __shared__ char smc[];
    const uint32_t sb = smem_u32(smc);
    const int tid = threadIdx.x;
    const int wid = tid >> 5, lane = tid & 31;

    int mode, bn, bm, batch = 0, kbase = 0, NK;
    const __half *A, *W;
    float* outp = nullptr;
    if (blockIdx.x < 512) {
        mode = 0;
        bn = (blockIdx.x & 7) * 128;
        bm = (blockIdx.x >> 3) * 128;
        A = g_hs; W = g_Wq;
        NK = D_ / 64;                  // 16
    } else {
        mode = 1;
        int r = blockIdx.x - 512;      // 8 bn x 8 bm x 16 z
        bn = (r & 7) * 128;
        bm = ((r >> 3) & 7) * 128;
        int z = r >> 6;
        batch = z & 1;
        int sel = (z >> 1) & 1;
        int split = z >> 2;
        if (bm >= g_cnt[batch]) return;
        A = g_pool;
        W = sel ? g_Wv : g_Wk;
        outp = g_KVp + ((size_t)(split * 2 + sel) * B_ + batch) * ((size_t)H_ * TP_ * DH_);
        kbase = split * (D_ / NSPLIT);
        NK = (D_ / NSPLIT) / 64;       // 4
    }

    auto load_stage = [&](int kt, int stage) {
        const uint32_t sbase = sb + stage * STAGE_BYTES;
        const int koff = kbase + kt * 64;
        #pragma unroll
        for (int i = 0; i < 8; i++) {
            int idx = tid + i * 256;
            int arr = idx >> 10;       // 0: A, 1: W
            int r = (idx >> 3) & 127;
            int c = idx & 7;
            const __half* src;
            if (arr == 0) {
                size_t row;
                if (mode == 0) row = (size_t)(bm + r);
                else row = (size_t)batch * TP_ + g_act[batch * TP_ + bm + r];
                src = A + row * D_ + koff + c * 8;
            } else {
                src = W + (size_t)(bn + r) * D_ + koff + c * 8;
            }
            CP_ASYNC16(sbase + arr * ARR_BYTES + r * RS_ + c * 16, src);
        }
        CP_COMMIT();
    };

    float acc[2][8][4];
    #pragma unroll
    for (int mt = 0; mt < 2; mt++)
        #pragma unroll
        for (int nt = 0; nt < 8; nt++)
            #pragma unroll
            for (int j = 0; j < 4; j++) acc[mt][nt][j] = 0.0f;

    const int wm = (wid & 3) * 32;
    const int wn = (wid >> 2) * 64;

    const int arw = (lane & 7) + ((lane >> 3) & 1) * 8;
    const int akh = lane >> 4;
    const int brw = (lane & 7) + (lane >> 4) * 8;
    const int bkh = (lane >> 3) & 1;
    const uint32_t aoff = (uint32_t)((wm + arw) * RS_ + akh * 16);
    const uint32_t boff = (uint32_t)(ARR_BYTES + (wn + brw) * RS_ + bkh * 16);

    load_stage(0, 0);

    for (int kt = 0; kt < NK; kt++) {
        if (kt + 1 < NK) {
            load_stage(kt + 1, (kt + 1) & 1);
            asm volatile("cp.async.wait_group 1;" ::: "memory");
        } else {
            asm volatile("cp.async.wait_group 0;" ::: "memory");
        }
        __syncthreads();

        const uint32_t st = sb + (kt & 1) * STAGE_BYTES;
        const uint32_t aB = st + aoff;
        const uint32_t bB = st + boff;

        #pragma unroll
        for (int j = 0; j < 4; j++) {              // four k16 chunks
            uint32_t af[2][4];
            ldsm_x4(af[0], aB + j * 32);
            ldsm_x4(af[1], aB + 16 * RS_ + j * 32);
            #pragma unroll
            for (int np = 0; np < 4; np++) {
                uint32_t bw[4];
                ldsm_x4(bw, bB + np * 16 * RS_ + j * 32);
                #pragma unroll
                for (int s = 0; s < 2; s++) {
                    const int nt = 2 * np + s;
                    #pragma unroll
                    for (int mt = 0; mt < 2; mt++)
                        mma_f16(acc[mt][nt], af[mt][0], af[mt][1], af[mt][2], af[mt][3], bw[2*s], bw[2*s+1]);
                }
            }
        }
        __syncthreads();
    }

    // ---- epilogue ----
    const int lr = lane >> 2;
    const int lc = (lane & 3) * 2;
    #pragma unroll
    for (int nt = 0; nt < 8; nt++) {
        int c0 = bn + wn + (nt >> 1) * 16 + (nt & 1) * 8 + lc;
        int h = c0 >> 6, d0 = c0 & 63;
        float2 b2 = make_float2(0.0f, 0.0f);
        if (mode == 0) b2 = *(const float2*)(bq_ + c0);
        #pragma unroll
        for (int mt = 0; mt < 2; mt++) {
            int m0 = bm + wm + mt * 16 + lr;
            #pragma unroll
            for (int half = 0; half < 2; half++) {
                int m = m0 + half * 8;
                if (mode == 0) {
                    int b = m >> 12, ls = m & (T_ - 1);
                    size_t dst = ((size_t)(b * H_ + h) * T_ + ls) * DH_ + d0;
                    float sx = (acc[mt][nt][2 * half + 0] + b2.x) * 0.125f;
                    float sy = (acc[mt][nt][2 * half + 1] + b2.y) * 0.125f;
                    __half hx = __float2half_rn(sx), hy = __float2half_rn(sy);
                    __half lx = __float2half_rn(sx - __half2float(hx));
                    __half ly = __float2half_rn(sy - __half2float(hy));
                    *(uint32_t*)(g_Qhi + dst) = packh2(hx, hy);
                    *(uint32_t*)(g_Qlo + dst) = packh2(lx, ly);
                } else {
                    size_t dst = ((size_t)h * TP_ + m) * DH_ + d0;
                    float2 o;
                    o.x = acc[mt][nt][2 * half + 0];
                    o.y = acc[mt][nt][2 * half + 1];
                    *(float2*)(outp + dst) = o;
                }
            }
        }
    }
}

// ---------------- 4) split-K reduce + bias -> K/V fp16 hi/lo -----------------
__global__ void kv_reduce_kernel(const float* __restrict__ bk,
                                 const float* __restrict__ bv) {
    int p = blockIdx.x * blockDim.x + threadIdx.x;
    int d4  = p & 15;
    int i   = (p >> 4) & (TP_ - 1);
    int h   = (p >> 14) & (H_ - 1);
    int b   = (p >> 18) & (B_ - 1);
    int sel = (p >> 19) & 1;
    size_t dsti = ((size_t)(b * H_ + h) * TP_ + i) * DH_ + d4 * 4;
    __half* outh = sel ? g_Vhi : g_Khi;
    __half* outl = sel ? g_Vlo : g_Klo;
    if (i >= g_cnt[b]) {
        *(uint2*)(outh + dsti) = make_uint2(0u, 0u);
        *(uint2*)(outl + dsti) = make_uint2(0u, 0u);
        return;
    }
    float4 acc = make_float4(0.f, 0.f, 0.f, 0.f);
    #pragma unroll
    for (int sp = 0; sp < NSPLIT; sp++) {
        const float* base = g_KVp
            + ((size_t)(sp * 2 + sel) * B_ + b) * ((size_t)H_ * TP_ * DH_)
            + ((size_t)h * TP_ + i) * DH_;
        float4 v = ((const float4*)base)[d4];
        acc.x += v.x; acc.y += v.y; acc.z += v.z; acc.w += v.w;
    }
    const float* bias = sel ? bv : bk;
    float4 bb = ((const float4*)(bias + h * DH_))[d4];
    acc.x += bb.x; acc.y += bb.y; acc.z += bb.z; acc.w += bb.w;
    __half hx = __float2half_rn(acc.x), hy = __float2half_rn(acc.y);
    __half hz = __float2half_rn(acc.z), hw = __float2half_rn(acc.w);
    uint2 hv, lv;
    hv.x = packh2(hx, hy); hv.y = packh2(hz, hw);
    lv.x = packh2(__float2half_rn(acc.x - __half2float(hx)),
                  __float2half_rn(acc.y - __half2float(hy)));
    lv.y = packh2(__float2half_rn(acc.z - __half2float(hz)),
                  __float2half_rn(acc.w - __half2float(hw)));
    *(uint2*)(outh + dsti) = hv;
    *(uint2*)(outl + dsti) = lv;
}

// ---------------- 5) fp16 tensor-core flash attention ------------------------
#define ATS 144
#define AARR (64 * ATS)
#define SM_KH (2 * AARR)
#define SM_VH (4 * AARR)
#define SMEM_ATTN (6 * AARR) // 55296

__global__ void __launch_bounds__(128, 4)
attn_kernel(float* __restrict__ out)
{
    extern __shared__ char smc[];
    const uint32_t sb = smem_u32(smc);
    const int tid = threadIdx.x, wid = tid >> 5, lane = tid & 31;
    const int b = blockIdx.z, h = blockIdx.y, q0 = blockIdx.x * 64;
    const int cnt = g_cnt[b];
    const int ntiles = (cnt + 63) >> 6;

    const __half* Qhp = g_Qhi + ((size_t)(b * H_ + h) * T_ + q0) * DH_;
    const __half* Qlp = g_Qlo + ((size_t)(b * H_ + h) * T_ + q0) * DH_;
    const size_t kvoff = (size_t)(b * H_ + h) * TP_ * DH_;
    const __half* kvsrc[4] = { g_Khi + kvoff, g_Klo + kvoff,
                               g_Vhi + kvoff, g_Vlo + kvoff };

    #pragma unroll
    for (int i = 0; i < 8; i++) {
        int idx = tid + i * 128;
        int arr = idx >> 9, r = (idx >> 3) & 63, c = idx & 7;
        const __half* src = (arr ? Qlp : Qhp) + (size_t)r * DH_ + c * 8;
        CP_ASYNC16(sb + arr * AARR + r * ATS + c * 16, src);
    }
    CP_COMMIT();

    float acc[8][4];
    #pragma unroll
    for (int nt = 0; nt < 8; nt++)
        #pragma unroll
        for (int j = 0; j < 4; j++) acc[nt][j] = 0.0f;
    float mrow[2] = { -1e30f, -1e30f };
    float lrow[2] = { 0.0f, 0.0f };

    const int lr = lane >> 2, lq = lane & 3;
    const int arw = (lane & 7) + ((lane >> 3) & 1) * 8;
    const int akh = lane >> 4;
    const int brw = (lane & 7) + (lane >> 4) * 8;
    const int bkh = (lane >> 3) & 1;
    const int vrw = (lane & 7) + ((lane >> 3) & 1) * 8;
    const int vc16 = (lane >> 4) * 16;

    const uint32_t qbase = sb + (wid * 16 + arw) * ATS + akh * 16;
    const uint32_t kbase = sb + SM_KH + brw * ATS + bkh * 16;
    const uint32_t vbase = sb + SM_VH + vrw * ATS + vc16;

    for (int t = 0; t < ntiles; t++) {
        const int kb = t * 64;
        #pragma unroll
        for (int i = 0; i < 16; i++) {
            int idx = tid + i * 128;
            int arr = idx >> 9, r = (idx >> 3) & 63, c = idx & 7;
            CP_ASYNC16(sb + SM_KH + arr * AARR + r * ATS + c * 16,
                       kvsrc[arr] + (size_t)(kb + r) * DH_ + c * 8);
        }
        CP_COMMIT();
        asm volatile("cp.async.wait_group 0;" ::: "memory");
        __syncthreads();

        float sc[8][4];
        #pragma unroll
        for (int nt = 0; nt < 8; nt++)
            #pragma unroll
            for (int j = 0; j < 4; j++) sc[nt][j] = 0.0f;
        #pragma unroll
        for (int j = 0; j < 4; j++) {
            uint32_t qh[4], ql[4];
            ldsm_x4(qh, qbase + j * 32);
            ldsm_x4(ql, qbase + AARR + j * 32);
            #pragma unroll
            for (int np = 0; np < 4; np++) {
                uint32_t kh4[4], kl4[4];
                ldsm_x4(kh4, kbase + np * 16 * ATS + j * 32);
                ldsm_x4(kl4, kbase + AARR + np * 16 * ATS + j * 32);
                #pragma unroll
                for (int s = 0; s < 2; s++) {
                    const int nt = 2 * np + s;
                    mma_f16(sc[nt], qh[0], qh[1], qh[2], qh[3], kh4[2*s], kh4[2*s+1]);
                    mma_f16(sc[nt], qh[0], qh[1], qh[2], qh[3], kl4[2*s], kl4[2*s+1]);
                    mma_f16(sc[nt], ql[0], ql[1], ql[2], ql[3], kh4[2*s], kh4[2*s+1]);
                }
            }
        }

        #pragma unroll
        for (int nt = 0; nt < 8; nt++) {
            int key = kb + nt * 8 + lq * 2;
            if (key >= cnt)     { sc[nt][0] = -1e30f; sc[nt][2] = -1e30f; }
            if (key + 1 >= cnt) { sc[nt][1] = -1e30f; sc[nt][3] = -1e30f; }
        }

        float tm0 = -1e30f, tm1 = -1e30f;
        #pragma unroll
        for (int nt = 0; nt < 8; nt++) {
            tm0 = fmaxf(tm0, fmaxf(sc[nt][0], sc[nt][1]));
            tm1 = fmaxf(tm1, fmaxf(sc[nt][2], sc[nt][3]));
        }
        tm0 = fmaxf(tm0, __shfl_xor_sync(0xffffffffu, tm0, 1));
        tm0 = fmaxf(tm0, __shfl_xor_sync(0xffffffffu, tm0, 2));
        tm1 = fmaxf(tm1, __shfl_xor_sync(0xffffffffu, tm1, 1));
        tm1 = fmaxf(tm1, __shfl_xor_sync(0xffffffffu, tm1, 2));
        const float mn0 = fmaxf(mrow[0], tm0);
        const float mn1 = fmaxf(mrow[1], tm1);
        const float al0 = __expf(mrow[0] - mn0);
        const float al1 = __expf(mrow[1] - mn1);

        uint32_t pAh[4][4], pAl[4][4];
        float ts0 = 0.0f, ts1 = 0.0f;
        #pragma unroll
        for (int nt = 0; nt < 8; nt++) {
            float p0 = __expf(sc[nt][0] - mn0);
            float p1 = __expf(sc[nt][1] - mn0);
            float p2 = __expf(sc[nt][2] - mn1);
            float p3 = __expf(sc[nt][3] - mn1);
            ts0 += p0 + p1;
            ts1 += p2 + p3;
            __half h0 = __float2half_rn(p0), h1 = __float2half_rn(p1);
            __half h2 = __float2half_rn(p2), h3 = __float2half_rn(p3);
            __half e0 = __float2half_rn(p0 - __half2float(h0));
            __half e1 = __float2half_rn(p1 - __half2float(h1));
            __half e2 = __float2half_rn(p2 - __half2float(h2));
            __half e3 = __float2half_rn(p3 - __half2float(h3));
            const int j = nt >> 1, o = (nt & 1) * 2;
            pAh[j][o]     = packh2(h0, h1);
            pAh[j][o + 1] = packh2(h2, h3);
            pAl[j][o]     = packh2(e0, e1);
            pAl[j][o + 1] = packh2(e2, e3);
        }
        ts0 += __shfl_xor_sync(0xffffffffu, ts0, 1);
        ts0 += __shfl_xor_sync(0xffffffffu, ts0, 2);
        ts1 += __shfl_xor_sync(0xffffffffu, ts1, 1);
        ts1 += __shfl_xor_sync(0xffffffffu, ts1, 2);
        lrow[0] = lrow[0] * al0 + ts0;
        lrow[1] = lrow[1] * al1 + ts1;
        mrow[0] = mn0;
        mrow[1] = mn1;
        #pragma unroll
        for (int nt = 0; nt < 8; nt++) {
            acc[nt][0] *= al0; acc[nt][1] *= al0;
            acc[nt][2] *= al1; acc[nt][3] *= al1;
        }

        #pragma unroll
        for (int j = 0; j < 4; j++) {
            #pragma unroll
            for (int np = 0; np < 4; np++) {
                uint32_t vh4[4], vl4[4];
                ldsm_x4t(vh4, vbase + (j * 16) * ATS + np * 32);
                ldsm_x4t(vl4, vbase + AARR + (j * 16) * ATS + np * 32);
                #pragma unroll
                for (int s = 0; s < 2; s++) {
                    const int nt = 2 * np + s;
                    mma_f16(acc[nt], pAh[j][0], pAh[j][1], pAh[j][2], pAh[j][3], vh4[2*s], vh4[2*s+1]);
                    mma_f16(acc[nt], pAh[j][0], pAh[j][1], pAh[j][2], pAh[j][3], vl4[2*s], vl4[2*s+1]);
                    mma_f16(acc[nt], pAl[j][0], pAl[j][1], pAl[j][2], pAl[j][3], vh4[2*s], vh4[2*s+1]);
                }
            }
        }
        __syncthreads();
    }

    const float inv0 = 1.0f / lrow[0];
    const float inv1 = 1.0f / lrow[1];
    const int row0 = q0 + wid * 16 + lr;
    #pragma unroll
    for (int nt = 0; nt < 8; nt++) {
        int dh = nt * 8 + lq * 2;
        float2 o;
        o.x = acc[nt][0] * inv0; o.y = acc[nt][1] * inv0;
        *(float2*)(out + ((size_t)b * T_ + row0) * D_ + h * DH_ + dh) = o;
        o.x = acc[nt][2] * inv1; o.y = acc[nt][3] * inv1;
        *(float2*)(out + ((size_t)b * T_ + row0 + 8) * D_ + h * DH_ + dh) = o;
    }
}

// ---------------- launch -----------------------------------------------------
extern "C" void kernel_launch(void* const* d_in, const int* in_sizes, int n_in,
                              void* d_out, int out_size) {
    const float* hs = (const float*)d_in[0];
    const int*   am = (const int*)d_in[1];
    const float* Wq = (const float*)d_in[2];
    const float* bq = (const float*)d_in[3];
    const float* Wk = (const float*)d_in[4];
    const float* bk = (const float*)d_in[5];
    const float* Wv = (const float*)d_in[6];
    const float* bv = (const float*)d_in[7];
    float* out = (float*)d_out;

    cudaFuncSetAttribute(gemm_fused_kernel, cudaFuncAttributeMaxDynamicSharedMemorySize, SMEM_GEMM);
    cudaFuncSetAttribute(attn_kernel, cudaFuncAttributeMaxDynamicSharedMemorySize, SMEM_ATTN);

    prep_kernel<<<(3 * W4_ + HS4_) / 256, 256>>>(hs, Wq, Wk, Wv);
    mask_kernel<<<B_, TP_>>>(am);
    gemm_fused_kernel<<<512 + 1024, 256, SMEM_GEMM>>>(bq);
    kv_reduce_kernel<<<(2 * B_ * H_ * TP_ * (DH_ / 4)) / 256, 256>>>(bk, bv);
    attn_kernel<<<dim3(T_ / 64, H_, B_), 128, SMEM_ATTN>>>(out);
}